// round 11
// baseline (speedup 1.0000x reference)
#include <cuda_runtime.h>
#include <cuda_fp16.h>
#include <math.h>

#define NB    32
#define EDIM  256
#define NHEAD 8
#define KDIM  16
#define VDIM  64
#define DHD   512
#define HQ    768
#define NPIX  400
#define SPIX  196
#define SA    36    // Ws row stride (words); also xT X-tile row stride
#define SBX   72    // Xs row stride (words), non-transposed
#define WW    4608  // W tile words per buffer (128*36)
#define XW    2304  // X tile words per buffer (32*72 == 64*36)
#define GSMEM ((2*WW + 2*XW) * 4)   // 55296 B dynamic smem for k_gemm_a
#define QTP   24    // Khi/Klo row stride (halves)
#define VHP   408   // Vh row stride (halves)
#define QSC   0.3606737602222409f   // 0.25 * log2(e)
#define L2E   1.4426950408889634f

typedef unsigned long long ull;

__device__ __forceinline__ float ex2f(float x) {
    float y; asm("ex2.approx.ftz.f32 %0, %1;" : "=f"(y) : "f"(x)); return y;
}
__device__ __forceinline__ void mma8(float* c, unsigned a0, unsigned a1, unsigned a2, unsigned a3,
                                     unsigned b0, unsigned b1) {
    asm volatile("mma.sync.aligned.m16n8k8.row.col.f32.tf32.tf32.f32 "
        "{%0,%1,%2,%3}, {%4,%5,%6,%7}, {%8,%9}, {%0,%1,%2,%3};"
        : "+f"(c[0]), "+f"(c[1]), "+f"(c[2]), "+f"(c[3])
        : "r"(a0), "r"(a1), "r"(a2), "r"(a3), "r"(b0), "r"(b1));
}
__device__ __forceinline__ void mmah(float* c, unsigned a0, unsigned a1, unsigned a2, unsigned a3,
                                     unsigned b0, unsigned b1) {
    asm volatile("mma.sync.aligned.m16n8k16.row.col.f32.f16.f16.f32 "
        "{%0,%1,%2,%3}, {%4,%5,%6,%7}, {%8,%9}, {%0,%1,%2,%3};"
        : "+f"(c[0]), "+f"(c[1]), "+f"(c[2]), "+f"(c[3])
        : "r"(a0), "r"(a1), "r"(a2), "r"(a3), "r"(b0), "r"(b1));
}
__device__ __forceinline__ void spl(float x, __half& hi, __half& lo) {
    hi = __float2half(x);
    lo = __float2half(x - __half2float(hi));
}
__device__ __forceinline__ unsigned pack2(__half a, __half b) {
    return (unsigned)__half_as_ushort(a) | ((unsigned)__half_as_ushort(b) << 16);
}
__device__ __forceinline__ unsigned saddr(const void* p) {
    return (unsigned)__cvta_generic_to_shared(p);
}
// 16B async copy; src_bytes==0 -> zero-fill (no global access)
__device__ __forceinline__ void cpa16(unsigned dst, const void* src, int src_bytes) {
    asm volatile("cp.async.cg.shared.global [%0], [%1], 16, %2;"
        :: "r"(dst), "l"(src), "r"(src_bytes));
}
__device__ __forceinline__ void cpa_commit() {
    asm volatile("cp.async.commit_group;");
}
template<int N> __device__ __forceinline__ void cpa_wait() {
    asm volatile("cp.async.wait_group %0;" :: "n"(N));
}

// ---------------- device scratch ----------------
__device__ __align__(16) float g_qkv [NB*HQ*NPIX];
__device__ __align__(16) float g_qdw [NB*128*NPIX];     // pre-scaled by QSC
__device__ __align__(16) float g_tmpb[NHEAD*NPIX*SPIX];
__device__ __align__(16) float g_bias[NHEAD*NPIX*NPIX]; // fragment layout [h][qt][kc][lane][8], *L2E
__device__ __align__(16) float g_ot  [NB*NPIX*DHD];     // relu'd attention output
__device__ __align__(16) float g_y1  [NB*EDIM*NPIX];
__device__ __align__(16) float g_hb  [NB*DHD*NPIX];
__device__ int   g_midx[NPIX*4];
__device__ float g_mw  [NPIX*4];

// ---------------- bicubic taps ----------------
__global__ void k_mtaps() {
    int i = blockIdx.x*blockDim.x + threadIdx.x;
    if (i >= NPIX) return;
    double scale = (double)SPIX / (double)NPIX;
    double src = (i + 0.5)*scale - 0.5;
    double f = floor(src);
    double t = src - f;
    const double a = -0.75;
    for (int j = -1; j <= 2; j++) {
        double xx = fabs((double)j - t);
        double w;
        if (xx <= 1.0)      w = (a+2.0)*xx*xx*xx - (a+3.0)*xx*xx + 1.0;
        else if (xx < 2.0)  w = a*xx*xx*xx - 5.0*a*xx*xx + 8.0*a*xx - 4.0*a;
        else                w = 0.0;
        int idx = (int)f + j;
        idx = min(max(idx, 0), SPIX-1);
        g_midx[i*4 + (j+1)] = idx;
        g_mw  [i*4 + (j+1)] = (float)w;
    }
}

__global__ void k_bias1(const float* __restrict__ ab, const int* __restrict__ idxs) {
    int i = blockIdx.x*blockDim.x + threadIdx.x;
    if (i >= NHEAD*NPIX*SPIX) return;
    int t = i % SPIX;
    int n = (i / SPIX) % NPIX;
    int h = i / (SPIX*NPIX);
    float acc = 0.f;
    #pragma unroll
    for (int k = 0; k < 4; k++) {
        int s = g_midx[n*4+k];
        acc += g_mw[n*4+k] * ab[h*SPIX + idxs[s*SPIX + t]];
    }
    g_tmpb[i] = acc;
}

// bias in m16n8k16 C-fragment order: out[h][qt][kc][lane][j] = L2E * bias(h,q,k)
__global__ void k_bias2() {
    int i = blockIdx.x*blockDim.x + threadIdx.x;
    if (i >= NHEAD*25*25*32*8) return;
    int j    = i & 7;
    int lane = (i >> 3) & 31;
    int kc   = (i >> 8) % 25;
    int qt   = ((i >> 8) / 25) % 25;
    int h    = (i >> 8) / 625;
    int g = lane >> 2, tg = lane & 3;
    int dr = ((j >> 1) & 1) * 8;
    int dc = 2*tg + (j & 1) + ((j >= 4) ? 8 : 0);
    int q = qt*16 + g + dr;
    int k = kc*16 + dc;
    const float* trow = g_tmpb + ((size_t)h*NPIX + q)*SPIX;
    float acc = 0.f;
    #pragma unroll
    for (int kk = 0; kk < 4; kk++)
        acc += g_mw[k*4+kk] * trow[g_midx[k*4+kk]];
    g_bias[i] = acc * L2E;
}

// ---------------- depthwise 3x3 (output pre-scaled by QSC) ----------------
__global__ void k_dwconv(const float* __restrict__ w, const float* __restrict__ s,
                         const float* __restrict__ bia) {
    int i = blockIdx.x*blockDim.x + threadIdx.x;
    if (i >= NB*128*NPIX) return;
    int p = i % NPIX;
    int c = (i / NPIX) % 128;
    int b = i / (128*NPIX);
    int y = p / 20, x = p % 20;
    const float* src = g_qkv + ((size_t)b*HQ + c)*NPIX;
    float acc = 0.f;
    #pragma unroll
    for (int dy = -1; dy <= 1; dy++) {
        int yy = y + dy;
        if (yy < 0 || yy >= 20) continue;
        #pragma unroll
        for (int dx = -1; dx <= 1; dx++) {
            int xx = x + dx;
            if (xx < 0 || xx >= 20) continue;
            acc += w[c*9 + (dy+1)*3 + (dx+1)] * src[yy*20 + xx];
        }
    }
    g_qdw[i] = (acc * s[c] + bia[c]) * QSC;
}

// ---------------- cp.async double-buffered tf32 GEMM (dynamic smem) --------
// Raw f32 bits fed to mma.tf32 (HW mantissa truncation; no cvt).
// flags: bit1 reluOut, bit2 X transposed [b][p][Cin]
__global__ void __launch_bounds__(256, 3) k_gemm_a(
    const float* __restrict__ X, const float* __restrict__ W,
    const float* __restrict__ sc, const float* __restrict__ bi,
    const float* __restrict__ R, float* __restrict__ Y,
    int O, int Cin, int flags)
{
    extern __shared__ __align__(16) unsigned gsm[];
    unsigned* WsBuf[2] = { gsm, gsm + WW };
    unsigned* XsBuf[2] = { gsm + 2*WW, gsm + 2*WW + XW };
    const int b  = blockIdx.z;
    const int oT = blockIdx.y * 128;
    const int pT = blockIdx.x * 64;
    const int t  = threadIdx.x;
    const int wid = t >> 5, lane = t & 31;
    const int g = lane >> 2, tg = lane & 3;
    const int warpM = wid & 3, warpN = wid >> 2;
    const bool reluOut = (flags & 2) != 0;
    const bool xT      = (flags & 4) != 0;

    float acc[2][4][4];
    #pragma unroll
    for (int mt = 0; mt < 2; mt++)
        #pragma unroll
        for (int nt = 0; nt < 4; nt++)
            #pragma unroll
            for (int i = 0; i < 4; i++) acc[mt][nt][i] = 0.f;

    const int nchunk = Cin >> 5;

    #define COPY_CHUNK(k0, buf)                                                     \
    {                                                                               \
        _Pragma("unroll")                                                           \
        for (int j = 0; j < 4; j++) {                                               \
            int qid = t + 256*j;                                                    \
            int row = qid >> 3, kq = (qid & 7) * 4;                                 \
            cpa16(saddr(&WsBuf[buf][row*SA + kq]),                                  \
                  &W[(size_t)(oT + row)*Cin + (k0) + kq], 16);                      \
        }                                                                           \
        if (!xT) {                                                                  \
            _Pragma("unroll")                                                       \
            for (int j = 0; j < 2; j++) {                                           \
                int qid = t + 256*j;                                                \
                int kx = qid >> 4, pl = (qid & 15) * 4;                             \
                int p  = pT + pl;                                                   \
                cpa16(saddr(&XsBuf[buf][kx*SBX + pl]),                              \
                      &X[((size_t)b*Cin + (k0) + kx)*NPIX + p],                     \
                      p < NPIX ? 16 : 0);                                           \
            }                                                                       \
        } else {                                                                    \
            _Pragma("unroll")                                                       \
            for (int j = 0; j < 2; j++) {                                           \
                int qid = t + 256*j;                                                \
                int pl = qid >> 3, kq = (qid & 7) * 4;                              \
                int p  = pT + pl;                                                   \
                cpa16(saddr(&XsBuf[buf][pl*SA + kq]),                               \
                      &X[((size_t)b*NPIX + p)*Cin + (k0) + kq],                     \
                      p < NPIX ? 16 : 0);                                           \
            }                                                                       \
        }                                                                           \
        cpa_commit();                                                               \
    }

    COPY_CHUNK(0, 0);

    for (int c = 0; c < nchunk; c++) {
        const int buf = c & 1;
        if (c + 1 < nchunk) {
            COPY_CHUNK((c+1)*32, (c+1) & 1);
            cpa_wait<1>();
        } else {
            cpa_wait<0>();
        }
        __syncthreads();

        const unsigned* Wb = WsBuf[buf];
        const unsigned* Xb = XsBuf[buf];
        #pragma unroll
        for (int ks = 0; ks < 4; ks++) {
            const int kk = ks * 8;
            unsigned a[2][4], bf[4][2];
            #pragma unroll
            for (int mt = 0; mt < 2; mt++) {
                const unsigned* Ab = &Wb[(warpM*32 + mt*16 + g)*SA + kk + tg];
                a[mt][0] = Ab[0];
                a[mt][1] = Ab[8*SA];
                a[mt][2] = Ab[4];
                a[mt][3] = Ab[8*SA + 4];
            }
            if (!xT) {
                #pragma unroll
                for (int nt = 0; nt < 4; nt++) {
                    const unsigned* Bb = &Xb[(kk + tg)*SBX + warpN*32 + nt*8 + g];
                    bf[nt][0] = Bb[0];
                    bf[nt][1] = Bb[4*SBX];
                }
            } else {
                #pragma unroll
                for (int nt = 0; nt < 4; nt++) {
                    const unsigned* Bb = &Xb[(warpN*32 + nt*8 + g)*SA + kk + tg];
                    bf[nt][0] = Bb[0];
                    bf[nt][1] = Bb[4];
                }
            }
            #pragma unroll
            for (int mt = 0; mt < 2; mt++)
                #pragma unroll
                for (int nt = 0; nt < 4; nt++)
                    mma8(acc[mt][nt], a[mt][0], a[mt][1], a[mt][2], a[mt][3],
                         bf[nt][0], bf[nt][1]);
        }
        __syncthreads();
    }
    #undef COPY_CHUNK

    // ---- epilogue ----
    #pragma unroll
    for (int mt = 0; mt < 2; mt++) {
        const int o0 = oT + warpM*32 + mt*16 + g;
        const int o1 = o0 + 8;
        const float s0 = sc[o0], bb0 = bi[o0];
        const float s1 = sc[o1], bb1 = bi[o1];
        #pragma unroll
        for (int nt = 0; nt < 4; nt++) {
            const int p = pT + warpN*32 + nt*8 + 2*tg;
            if (p < NPIX) {
                float2 v0, v1;
                v0.x = acc[mt][nt][0]*s0 + bb0;
                v0.y = acc[mt][nt][1]*s0 + bb0;
                v1.x = acc[mt][nt][2]*s1 + bb1;
                v1.y = acc[mt][nt][3]*s1 + bb1;
                if (reluOut) {
                    v0.x = fmaxf(v0.x,0.f); v0.y = fmaxf(v0.y,0.f);
                    v1.x = fmaxf(v1.x,0.f); v1.y = fmaxf(v1.y,0.f);
                }
                const size_t off0 = ((size_t)b*O + o0)*NPIX + p;
                const size_t off1 = ((size_t)b*O + o1)*NPIX + p;
                if (R) {
                    float2 r0 = *(const float2*)&R[off0];
                    float2 r1 = *(const float2*)&R[off1];
                    v0.x += r0.x; v0.y += r0.y;
                    v1.x += r1.x; v1.y += r1.y;
                }
                *(float2*)&Y[off0] = v0;
                *(float2*)&Y[off1] = v1;
            }
        }
    }
}

// ---------------- tensor-core flash attention, split-f16 ----------------
// (unchanged from R9 except relu fused into the output store)
__global__ void __launch_bounds__(256, 2) k_attn6() {
    extern __shared__ __half smh[];
    __half* Khi = smh;              // [400][QTP]
    __half* Klo = smh + 9600;       // [400][QTP]
    __half* Vh  = smh + 19200;      // [64][VHP]
    const int bh = blockIdx.x;
    const int b = bh >> 3, h = bh & 7;
    const int tid = threadIdx.x;

    const float* qb = g_qdw + ((size_t)b*128 + h*KDIM)*NPIX;
    const float* kb = g_qkv + ((size_t)b*HQ + 128 + h*KDIM)*NPIX;
    const float* vb = g_qkv + ((size_t)b*HQ + 256 + h*VDIM)*NPIX;

    for (int i = tid; i < KDIM*NPIX; i += 256) {
        int d = i / NPIX, p = i - d*NPIX;
        __half hi, lo; spl(kb[i], hi, lo);
        Khi[p*QTP + d] = hi;
        Klo[p*QTP + d] = lo;
    }
    for (int i = tid; i < VDIM*NPIX; i += 256) {
        int d = i / NPIX, p = i - d*NPIX;
        Vh[d*VHP + p] = __float2half(vb[i]);
    }
    __syncthreads();

    const int w = tid >> 5, lane = tid & 31;
    const int g = lane >> 2, tg = lane & 3;

    for (int tile = w; tile < 25; tile += 8) {
        const int q0 = tile * 16;
        unsigned qh[4], ql[4];
        {
            const int r0 = q0 + g, r1 = q0 + g + 8;
            const int d0 = 2*tg, d1 = 2*tg + 8;
            float q00a = qb[(d0  )*NPIX + r0], q00b = qb[(d0+1)*NPIX + r0];
            float q10a = qb[(d0  )*NPIX + r1], q10b = qb[(d0+1)*NPIX + r1];
            float q01a = qb[(d1  )*NPIX + r0], q01b = qb[(d1+1)*NPIX + r0];
            float q11a = qb[(d1  )*NPIX + r1], q11b = qb[(d1+1)*NPIX + r1];
            __half ha, la, hb2, lb2;
            spl(q00a, ha, la); spl(q00b, hb2, lb2);
            qh[0] = pack2(ha, hb2); ql[0] = pack2(la, lb2);
            spl(q10a, ha, la); spl(q10b, hb2, lb2);
            qh[1] = pack2(ha, hb2); ql[1] = pack2(la, lb2);
            spl(q01a, ha, la); spl(q01b, hb2, lb2);
            qh[2] = pack2(ha, hb2); ql[2] = pack2(la, lb2);
            spl(q11a, ha, la); spl(q11b, hb2, lb2);
            qh[3] = pack2(ha, hb2); ql[3] = pack2(la, lb2);
        }

        float o[8][4];
        #pragma unroll
        for (int dt = 0; dt < 8; dt++)
            #pragma unroll
            for (int i = 0; i < 4; i++) o[dt][i] = 0.f;
        float m_g = -1e30f, m_h = -1e30f, den_g = 0.f, den_h = 0.f;

        const float* bfrag = &g_bias[((((size_t)h*25 + tile)*25)*32 + lane)*8];

        for (int kc = 0; kc < 25; kc++) {
            const int k0 = kc * 16;
            float s0[4] = {0.f,0.f,0.f,0.f};
            float s1[4] = {0.f,0.f,0.f,0.f};
            {
                unsigned b0h = *(const unsigned*)&Khi[(k0+g)*QTP + 2*tg];
                unsigned b1h = *(const unsigned*)&Khi[(k0+g)*QTP + 2*tg + 8];
                unsigned b0l = *(const unsigned*)&Klo[(k0+g)*QTP + 2*tg];
                unsigned b1l = *(const unsigned*)&Klo[(k0+g)*QTP + 2*tg + 8];
                mmah(s0, qh[0], qh[1], qh[2], qh[3], b0h, b1h);
                mmah(s0, qh[0], qh[1], qh[2], qh[3], b0l, b1l);
                mmah(s0, ql[0], ql[1], ql[2], ql[3], b0h, b1h);
                unsigned c0h = *(const unsigned*)&Khi[(k0+8+g)*QTP + 2*tg];
                unsigned c1h = *(const unsigned*)&Khi[(k0+8+g)*QTP + 2*tg + 8];
                unsigned c0l = *(const unsigned*)&Klo[(k0+8+g)*QTP + 2*tg];
                unsigned c1l = *(const unsigned*)&Klo[(k0+8+g)*QTP + 2*tg + 8];
                mmah(s1, qh[0], qh[1], qh[2], qh[3], c0h, c1h);
                mmah(s1, qh[0], qh[1], qh[2], qh[3], c0l, c1l);
                mmah(s1, ql[0], ql[1], ql[2], ql[3], c0h, c1h);
            }
            const float4 bv0 = *(const float4*)(bfrag + (size_t)kc*256);
            const float4 bv1 = *(const float4*)(bfrag + (size_t)kc*256 + 4);
            s0[0] += bv0.x; s0[1] += bv0.y; s0[2] += bv0.z; s0[3] += bv0.w;
            s1[0] += bv1.x; s1[1] += bv1.y; s1[2] += bv1.z; s1[3] += bv1.w;
            float cmg = fmaxf(fmaxf(s0[0], s0[1]), fmaxf(s1[0], s1[1]));
            float cmh = fmaxf(fmaxf(s0[2], s0[3]), fmaxf(s1[2], s1[3]));
            cmg = fmaxf(cmg, __shfl_xor_sync(0xffffffffu, cmg, 1));
            cmg = fmaxf(cmg, __shfl_xor_sync(0xffffffffu, cmg, 2));
            cmh = fmaxf(cmh, __shfl_xor_sync(0xffffffffu, cmh, 1));
            cmh = fmaxf(cmh, __shfl_xor_sync(0xffffffffu, cmh, 2));
            if (__any_sync(0xffffffffu, (cmg > m_g) || (cmh > m_h))) {
                float nm_g = fmaxf(m_g, cmg), nm_h = fmaxf(m_h, cmh);
                float rg = ex2f(m_g - nm_g), rh = ex2f(m_h - nm_h);
                den_g *= rg; den_h *= rh;
                #pragma unroll
                for (int dt = 0; dt < 8; dt++) {
                    o[dt][0] *= rg; o[dt][1] *= rg;
                    o[dt][2] *= rh; o[dt][3] *= rh;
                }
                m_g = nm_g; m_h = nm_h;
            }
            float p00 = ex2f(s0[0] - m_g), p01 = ex2f(s0[1] - m_g);
            float p02 = ex2f(s0[2] - m_h), p03 = ex2f(s0[3] - m_h);
            float p10 = ex2f(s1[0] - m_g), p11 = ex2f(s1[1] - m_g);
            float p12 = ex2f(s1[2] - m_h), p13 = ex2f(s1[3] - m_h);
            den_g += (p00 + p01) + (p10 + p11);
            den_h += (p02 + p03) + (p12 + p13);
            unsigned ph[4], pl[4];
            {
                __half ha, la, hb2, lb2;
                spl(p00, ha, la); spl(p01, hb2, lb2);
                ph[0] = pack2(ha, hb2); pl[0] = pack2(la, lb2);
                spl(p02, ha, la); spl(p03, hb2, lb2);
                ph[1] = pack2(ha, hb2); pl[1] = pack2(la, lb2);
                spl(p10, ha, la); spl(p11, hb2, lb2);
                ph[2] = pack2(ha, hb2); pl[2] = pack2(la, lb2);
                spl(p12, ha, la); spl(p13, hb2, lb2);
                ph[3] = pack2(ha, hb2); pl[3] = pack2(la, lb2);
            }
            #pragma unroll
            for (int dt = 0; dt < 8; dt++) {
                unsigned vb0 = *(const unsigned*)&Vh[(dt*8+g)*VHP + k0 + 2*tg];
                unsigned vb1 = *(const unsigned*)&Vh[(dt*8+g)*VHP + k0 + 2*tg + 8];
                mmah(o[dt], ph[0], ph[1], ph[2], ph[3], vb0, vb1);
                mmah(o[dt], pl[0], pl[1], pl[2], pl[3], vb0, vb1);
            }
        }
        den_g += __shfl_xor_sync(0xffffffffu, den_g, 1);
        den_g += __shfl_xor_sync(0xffffffffu, den_g, 2);
        den_h += __shfl_xor_sync(0xffffffffu, den_h, 1);
        den_h += __shfl_xor_sync(0xffffffffu, den_h, 2);
        const float ig = 1.f / den_g, ih = 1.f / den_h;
        float* org = &g_ot[((size_t)b*NPIX + q0 + g)*DHD + h*VDIM];
        float* orh = &g_ot[((size_t)b*NPIX + q0 + g + 8)*DHD + h*VDIM];
        #pragma unroll
        for (int dt = 0; dt < 8; dt++) {
            float2 v0, v1;
            v0.x = fmaxf(o[dt][0] * ig, 0.f); v0.y = fmaxf(o[dt][1] * ig, 0.f);
            v1.x = fmaxf(o[dt][2] * ih, 0.f); v1.y = fmaxf(o[dt][3] * ih, 0.f);
            *(float2*)&org[dt*8 + 2*tg] = v0;
            *(float2*)&orh[dt*8 + 2*tg] = v1;
        }
    }
}

// ---------------- launch ----------------
extern "C" void kernel_launch(void* const* d_in, const int* in_sizes, int n_in,
                              void* d_out, int out_size) {
    const float* x      = (const float*)d_in[0];
    const float* qkv_w  = (const float*)d_in[1];
    const float* qkv_s  = (const float*)d_in[2];
    const float* qkv_b  = (const float*)d_in[3];
    const float* dw_w   = (const float*)d_in[4];
    const float* dw_s   = (const float*)d_in[5];
    const float* dw_b   = (const float*)d_in[6];
    const float* proj_w = (const float*)d_in[7];
    const float* proj_s = (const float*)d_in[8];
    const float* proj_b = (const float*)d_in[9];
    const float* ab     = (const float*)d_in[10];
    const float* pw1_w  = (const float*)d_in[11];
    const float* pw1_s  = (const float*)d_in[12];
    const float* pw1_b  = (const float*)d_in[13];
    const float* pw2_w  = (const float*)d_in[14];
    const float* pw2_s  = (const float*)d_in[15];
    const float* pw2_b  = (const float*)d_in[16];
    const int*   idxs   = (const int*)d_in[17];

    float *p_qkv, *p_ot, *p_y1, *p_hb;
    cudaGetSymbolAddress((void**)&p_qkv, g_qkv);
    cudaGetSymbolAddress((void**)&p_ot,  g_ot);
    cudaGetSymbolAddress((void**)&p_y1,  g_y1);
    cudaGetSymbolAddress((void**)&p_hb,  g_hb);

    cudaFuncSetAttribute(k_gemm_a, cudaFuncAttributeMaxDynamicSharedMemorySize, GSMEM);

    // bias pipeline
    k_mtaps<<<1, 512>>>();
    k_bias1<<<(NHEAD*NPIX*SPIX + 255)/256, 256>>>(ab, idxs);
    k_bias2<<<(NHEAD*25*25*32*8 + 255)/256, 256>>>();

    // qkv conv1x1
    k_gemm_a<<<dim3(7, HQ/128, NB), 256, GSMEM>>>(x, qkv_w, qkv_s, qkv_b, nullptr, p_qkv, HQ, EDIM, 0);
    // depthwise 3x3 on q
    k_dwconv<<<(NB*128*NPIX + 255)/256, 256>>>(dw_w, dw_s, dw_b);

    // tensor-core flash attention (relu fused into output store)
    const int smem = (9600 + 9600 + VDIM*VHP) * 2;  // 90624 B
    cudaFuncSetAttribute(k_attn6, cudaFuncAttributeMaxDynamicSharedMemorySize, smem);
    k_attn6<<<NB*NHEAD, 256, smem>>>();

    // proj (X transposed [b][p][512], residual x) -> y1
    k_gemm_a<<<dim3(7, EDIM/128, NB), 256, GSMEM>>>(p_ot, proj_w, proj_s, proj_b, x, p_y1, EDIM, DHD, 4);
    // pw1 (relu-out) -> h
    k_gemm_a<<<dim3(7, DHD/128, NB), 256, GSMEM>>>(p_y1, pw1_w, pw1_s, pw1_b, nullptr, p_hb, DHD, EDIM, 2);
    // pw2 (residual y1) -> out
    k_gemm_a<<<dim3(7, EDIM/128, NB), 256, GSMEM>>>(p_hb, pw2_w, pw2_s, pw2_b, p_y1, (float*)d_out, EDIM, DHD, 0);
}

// round 12
// speedup vs baseline: 1.1454x; 1.1454x over previous
#include <cuda_runtime.h>
#include <cuda_fp16.h>
#include <math.h>

#define NB    32
#define EDIM  256
#define NHEAD 8
#define KDIM  16
#define VDIM  64
#define DHD   512
#define HQ    768
#define NPIX  400
#define SPIX  196
#define WSP   40    // W smem row stride (halves): frag banks 20g+tg -> 32 distinct
#define XSP   40    // X smem row stride (halves): same property
#define QTP   24    // Khi/Klo row stride (halves)
#define VHP   408   // Vh row stride (halves)
#define QSC   0.3606737602222409f   // 0.25 * log2(e)
#define L2E   1.4426950408889634f

typedef unsigned long long ull;

__device__ __forceinline__ float ex2f(float x) {
    float y; asm("ex2.approx.ftz.f32 %0, %1;" : "=f"(y) : "f"(x)); return y;
}
__device__ __forceinline__ void mmah(float* c, unsigned a0, unsigned a1, unsigned a2, unsigned a3,
                                     unsigned b0, unsigned b1) {
    asm volatile("mma.sync.aligned.m16n8k16.row.col.f32.f16.f16.f32 "
        "{%0,%1,%2,%3}, {%4,%5,%6,%7}, {%8,%9}, {%0,%1,%2,%3};"
        : "+f"(c[0]), "+f"(c[1]), "+f"(c[2]), "+f"(c[3])
        : "r"(a0), "r"(a1), "r"(a2), "r"(a3), "r"(b0), "r"(b1));
}
// pack {lo, hi} floats into f16x2 (cvt packs FIRST source into the upper half)
__device__ __forceinline__ unsigned packh2(float lo, float hi) {
    unsigned d; asm("cvt.rn.f16x2.f32 %0, %1, %2;" : "=r"(d) : "f"(hi), "f"(lo)); return d;
}
__device__ __forceinline__ void spl(float x, __half& hi, __half& lo) {
    hi = __float2half(x);
    lo = __float2half(x - __half2float(hi));
}
__device__ __forceinline__ unsigned pack2(__half a, __half b) {
    return (unsigned)__half_as_ushort(a) | ((unsigned)__half_as_ushort(b) << 16);
}

// ---------------- device scratch ----------------
__device__ __align__(16) float g_qkv [NB*HQ*NPIX];
__device__ __align__(16) float g_qdw [NB*128*NPIX];     // pre-scaled by QSC
__device__ __align__(16) float g_tmpb[NHEAD*NPIX*SPIX];
__device__ __align__(16) float g_bias[NHEAD*NPIX*NPIX]; // fragment layout [h][qt][kc][lane][8], *L2E
__device__ __align__(16) float g_ot  [NB*NPIX*DHD];     // relu'd attention output
__device__ __align__(16) float g_y1  [NB*EDIM*NPIX];
__device__ __align__(16) float g_hb  [NB*DHD*NPIX];
__device__ int   g_midx[NPIX*4];
__device__ float g_mw  [NPIX*4];

// ---------------- bicubic taps ----------------
__global__ void k_mtaps() {
    int i = blockIdx.x*blockDim.x + threadIdx.x;
    if (i >= NPIX) return;
    double scale = (double)SPIX / (double)NPIX;
    double src = (i + 0.5)*scale - 0.5;
    double f = floor(src);
    double t = src - f;
    const double a = -0.75;
    for (int j = -1; j <= 2; j++) {
        double xx = fabs((double)j - t);
        double w;
        if (xx <= 1.0)      w = (a+2.0)*xx*xx*xx - (a+3.0)*xx*xx + 1.0;
        else if (xx < 2.0)  w = a*xx*xx*xx - 5.0*a*xx*xx + 8.0*a*xx - 4.0*a;
        else                w = 0.0;
        int idx = (int)f + j;
        idx = min(max(idx, 0), SPIX-1);
        g_midx[i*4 + (j+1)] = idx;
        g_mw  [i*4 + (j+1)] = (float)w;
    }
}

__global__ void k_bias1(const float* __restrict__ ab, const int* __restrict__ idxs) {
    int i = blockIdx.x*blockDim.x + threadIdx.x;
    if (i >= NHEAD*NPIX*SPIX) return;
    int t = i % SPIX;
    int n = (i / SPIX) % NPIX;
    int h = i / (SPIX*NPIX);
    float acc = 0.f;
    #pragma unroll
    for (int k = 0; k < 4; k++) {
        int s = g_midx[n*4+k];
        acc += g_mw[n*4+k] * ab[h*SPIX + idxs[s*SPIX + t]];
    }
    g_tmpb[i] = acc;
}

// bias in m16n8k16 C-fragment order: out[h][qt][kc][lane][j] = L2E * bias(h,q,k)
__global__ void k_bias2() {
    int i = blockIdx.x*blockDim.x + threadIdx.x;
    if (i >= NHEAD*25*25*32*8) return;
    int j    = i & 7;
    int lane = (i >> 3) & 31;
    int kc   = (i >> 8) % 25;
    int qt   = ((i >> 8) / 25) % 25;
    int h    = (i >> 8) / 625;
    int g = lane >> 2, tg = lane & 3;
    int dr = ((j >> 1) & 1) * 8;
    int dc = 2*tg + (j & 1) + ((j >= 4) ? 8 : 0);
    int q = qt*16 + g + dr;
    int k = kc*16 + dc;
    const float* trow = g_tmpb + ((size_t)h*NPIX + q)*SPIX;
    float acc = 0.f;
    #pragma unroll
    for (int kk = 0; kk < 4; kk++)
        acc += g_mw[k*4+kk] * trow[g_midx[k*4+kk]];
    g_bias[i] = acc * L2E;
}

// ---------------- depthwise 3x3 (output pre-scaled by QSC) ----------------
__global__ void k_dwconv(const float* __restrict__ w, const float* __restrict__ s,
                         const float* __restrict__ bia) {
    int i = blockIdx.x*blockDim.x + threadIdx.x;
    if (i >= NB*128*NPIX) return;
    int p = i % NPIX;
    int c = (i / NPIX) % 128;
    int b = i / (128*NPIX);
    int y = p / 20, x = p % 20;
    const float* src = g_qkv + ((size_t)b*HQ + c)*NPIX;
    float acc = 0.f;
    #pragma unroll
    for (int dy = -1; dy <= 1; dy++) {
        int yy = y + dy;
        if (yy < 0 || yy >= 20) continue;
        #pragma unroll
        for (int dx = -1; dx <= 1; dx++) {
            int xx = x + dx;
            if (xx < 0 || xx >= 20) continue;
            acc += w[c*9 + (dy+1)*3 + (dx+1)] * src[yy*20 + xx];
        }
    }
    g_qdw[i] = (acc * s[c] + bia[c]) * QSC;
}

// ---------------- f16 m16n8k16 tensor-core GEMM ----------------
// Ws [128 rows][WSP halves] (A, row-major k-contig), Xs [64 cols][XSP halves]
// (B, n-major k-contig). CTA tile 128(O) x 64(p), 8 warps 4x2, warp 32x32.
// flags: bit1 reluOut, bit2 X transposed [b][p][Cin]
__global__ void __launch_bounds__(256, 3) k_gemm_h(
    const float* __restrict__ X, const float* __restrict__ W,
    const float* __restrict__ sc, const float* __restrict__ bi,
    const float* __restrict__ R, float* __restrict__ Y,
    int O, int Cin, int flags)
{
    __shared__ __align__(16) __half Ws[128*WSP];
    __shared__ __align__(16) __half Xs[64*XSP];
    const int b  = blockIdx.z;
    const int oT = blockIdx.y * 128;
    const int pT = blockIdx.x * 64;
    const int t  = threadIdx.x;
    const int wid = t >> 5, lane = t & 31;
    const int g = lane >> 2, tg = lane & 3;
    const int warpM = wid & 3, warpN = wid >> 2;
    const bool reluOut = (flags & 2) != 0;
    const bool xT      = (flags & 4) != 0;

    float acc[2][4][4];
    #pragma unroll
    for (int mt = 0; mt < 2; mt++)
        #pragma unroll
        for (int nt = 0; nt < 4; nt++)
            #pragma unroll
            for (int i = 0; i < 4; i++) acc[mt][nt][i] = 0.f;

    const int nchunk = Cin >> 5;

    for (int c = 0; c < nchunk; c++) {
        const int k0 = c * 32;
        // ---- W tile: 128 rows x 32 k ----
        #pragma unroll
        for (int j = 0; j < 4; j++) {
            int qid = t + 256*j;
            int row = qid >> 3, kq = (qid & 7) * 4;
            float4 wv = *(const float4*)&W[(size_t)(oT + row)*Cin + k0 + kq];
            unsigned h01 = packh2(wv.x, wv.y);
            unsigned h23 = packh2(wv.z, wv.w);
            *(uint2*)&Ws[row*WSP + kq] = make_uint2(h01, h23);
        }
        // ---- X tile -> [col p][k] halves ----
        if (!xT) {
            // global [ci][p]: transpose; 2 k per thread per slot
            #pragma unroll
            for (int j = 0; j < 4; j++) {
                int qid = t + 256*j;
                int p  = qid & 63;
                int k  = (qid >> 6) * 2;
                int gp = pT + p;
                float x0 = 0.f, x1 = 0.f;
                if (gp < NPIX) {
                    const float* xp = &X[((size_t)b*Cin + k0 + k)*NPIX + gp];
                    x0 = xp[0];
                    x1 = xp[NPIX];
                }
                *(unsigned*)&Xs[p*XSP + k] = packh2(x0, x1);
            }
        } else {
            // global [p][Cin]: k contiguous already
            #pragma unroll
            for (int j = 0; j < 2; j++) {
                int qid = t + 256*j;
                int p  = qid >> 3, kq = (qid & 7) * 4;
                int gp = pT + p;
                float4 xv = make_float4(0.f,0.f,0.f,0.f);
                if (gp < NPIX)
                    xv = *(const float4*)&X[((size_t)b*NPIX + gp)*Cin + k0 + kq];
                unsigned h01 = packh2(xv.x, xv.y);
                unsigned h23 = packh2(xv.z, xv.w);
                *(uint2*)&Xs[p*XSP + kq] = make_uint2(h01, h23);
            }
        }
        __syncthreads();

        #pragma unroll
        for (int ks = 0; ks < 2; ks++) {
            const int kk = ks * 16;
            unsigned a[2][4], bf[4][2];
            #pragma unroll
            for (int mt = 0; mt < 2; mt++) {
                const __half* Ab = &Ws[(warpM*32 + mt*16 + g)*WSP + kk + 2*tg];
                a[mt][0] = *(const unsigned*)(Ab);
                a[mt][1] = *(const unsigned*)(Ab + 8*WSP);
                a[mt][2] = *(const unsigned*)(Ab + 8);
                a[mt][3] = *(const unsigned*)(Ab + 8*WSP + 8);
            }
            #pragma unroll
            for (int nt = 0; nt < 4; nt++) {
                const __half* Bb = &Xs[(warpN*32 + nt*8 + g)*XSP + kk + 2*tg];
                bf[nt][0] = *(const unsigned*)(Bb);
                bf[nt][1] = *(const unsigned*)(Bb + 8);
            }
            #pragma unroll
            for (int mt = 0; mt < 2; mt++)
                #pragma unroll
                for (int nt = 0; nt < 4; nt++)
                    mmah(acc[mt][nt], a[mt][0], a[mt][1], a[mt][2], a[mt][3],
                         bf[nt][0], bf[nt][1]);
        }
        __syncthreads();
    }

    // ---- epilogue (C-frag: c0,c1 = row g cols 2tg,2tg+1; c2,c3 = row g+8) ----
    #pragma unroll
    for (int mt = 0; mt < 2; mt++) {
        const int o0 = oT + warpM*32 + mt*16 + g;
        const int o1 = o0 + 8;
        const float s0 = sc[o0], bb0 = bi[o0];
        const float s1 = sc[o1], bb1 = bi[o1];
        #pragma unroll
        for (int nt = 0; nt < 4; nt++) {
            const int p = pT + warpN*32 + nt*8 + 2*tg;
            if (p < NPIX) {
                float2 v0, v1;
                v0.x = acc[mt][nt][0]*s0 + bb0;
                v0.y = acc[mt][nt][1]*s0 + bb0;
                v1.x = acc[mt][nt][2]*s1 + bb1;
                v1.y = acc[mt][nt][3]*s1 + bb1;
                if (reluOut) {
                    v0.x = fmaxf(v0.x,0.f); v0.y = fmaxf(v0.y,0.f);
                    v1.x = fmaxf(v1.x,0.f); v1.y = fmaxf(v1.y,0.f);
                }
                const size_t off0 = ((size_t)b*O + o0)*NPIX + p;
                const size_t off1 = ((size_t)b*O + o1)*NPIX + p;
                if (R) {
                    float2 r0 = *(const float2*)&R[off0];
                    float2 r1 = *(const float2*)&R[off1];
                    v0.x += r0.x; v0.y += r0.y;
                    v1.x += r1.x; v1.y += r1.y;
                }
                *(float2*)&Y[off0] = v0;
                *(float2*)&Y[off1] = v1;
            }
        }
    }
}

// ---------------- tensor-core flash attention, split-f16 ----------------
// (unchanged from R11; relu fused into the output store)
__global__ void __launch_bounds__(256, 2) k_attn6() {
    extern __shared__ __half smh[];
    __half* Khi = smh;              // [400][QTP]
    __half* Klo = smh + 9600;       // [400][QTP]
    __half* Vh  = smh + 19200;      // [64][VHP]
    const int bh = blockIdx.x;
    const int b = bh >> 3, h = bh & 7;
    const int tid = threadIdx.x;

    const float* qb = g_qdw + ((size_t)b*128 + h*KDIM)*NPIX;
    const float* kb = g_qkv + ((size_t)b*HQ + 128 + h*KDIM)*NPIX;
    const float* vb = g_qkv + ((size_t)b*HQ + 256 + h*VDIM)*NPIX;

    for (int i = tid; i < KDIM*NPIX; i += 256) {
        int d = i / NPIX, p = i - d*NPIX;
        __half hi, lo; spl(kb[i], hi, lo);
        Khi[p*QTP + d] = hi;
        Klo[p*QTP + d] = lo;
    }
    for (int i = tid; i < VDIM*NPIX; i += 256) {
        int d = i / NPIX, p = i - d*NPIX;
        Vh[d*VHP + p] = __float2half(vb[i]);
    }
    __syncthreads();

    const int w = tid >> 5, lane = tid & 31;
    const int g = lane >> 2, tg = lane & 3;

    for (int tile = w; tile < 25; tile += 8) {
        const int q0 = tile * 16;
        unsigned qh[4], ql[4];
        {
            const int r0 = q0 + g, r1 = q0 + g + 8;
            const int d0 = 2*tg, d1 = 2*tg + 8;
            float q00a = qb[(d0  )*NPIX + r0], q00b = qb[(d0+1)*NPIX + r0];
            float q10a = qb[(d0  )*NPIX + r1], q10b = qb[(d0+1)*NPIX + r1];
            float q01a = qb[(d1  )*NPIX + r0], q01b = qb[(d1+1)*NPIX + r0];
            float q11a = qb[(d1  )*NPIX + r1], q11b = qb[(d1+1)*NPIX + r1];
            __half ha, la, hb2, lb2;
            spl(q00a, ha, la); spl(q00b, hb2, lb2);
            qh[0] = pack2(ha, hb2); ql[0] = pack2(la, lb2);
            spl(q10a, ha, la); spl(q10b, hb2, lb2);
            qh[1] = pack2(ha, hb2); ql[1] = pack2(la, lb2);
            spl(q01a, ha, la); spl(q01b, hb2, lb2);
            qh[2] = pack2(ha, hb2); ql[2] = pack2(la, lb2);
            spl(q11a, ha, la); spl(q11b, hb2, lb2);
            qh[3] = pack2(ha, hb2); ql[3] = pack2(la, lb2);
        }

        float o[8][4];
        #pragma unroll
        for (int dt = 0; dt < 8; dt++)
            #pragma unroll
            for (int i = 0; i < 4; i++) o[dt][i] = 0.f;
        float m_g = -1e30f, m_h = -1e30f, den_g = 0.f, den_h = 0.f;

        const float* bfrag = &g_bias[((((size_t)h*25 + tile)*25)*32 + lane)*8];

        for (int kc = 0; kc < 25; kc++) {
            const int k0 = kc * 16;
            float s0[4] = {0.f,0.f,0.f,0.f};
            float s1[4] = {0.f,0.f,0.f,0.f};
            {
                unsigned b0h = *(const unsigned*)&Khi[(k0+g)*QTP + 2*tg];
                unsigned b1h = *(const unsigned*)&Khi[(k0+g)*QTP + 2*tg + 8];
                unsigned b0l = *(const unsigned*)&Klo[(k0+g)*QTP + 2*tg];
                unsigned b1l = *(const unsigned*)&Klo[(k0+g)*QTP + 2*tg + 8];
                mmah(s0, qh[0], qh[1], qh[2], qh[3], b0h, b1h);
                mmah(s0, qh[0], qh[1], qh[2], qh[3], b0l, b1l);
                mmah(s0, ql[0], ql[1], ql[2], ql[3], b0h, b1h);
                unsigned c0h = *(const unsigned*)&Khi[(k0+8+g)*QTP + 2*tg];
                unsigned c1h = *(const unsigned*)&Khi[(k0+8+g)*QTP + 2*tg + 8];
                unsigned c0l = *(const unsigned*)&Klo[(k0+8+g)*QTP + 2*tg];
                unsigned c1l = *(const unsigned*)&Klo[(k0+8+g)*QTP + 2*tg + 8];
                mmah(s1, qh[0], qh[1], qh[2], qh[3], c0h, c1h);
                mmah(s1, qh[0], qh[1], qh[2], qh[3], c0l, c1l);
                mmah(s1, ql[0], ql[1], ql[2], ql[3], c0h, c1h);
            }
            const float4 bv0 = *(const float4*)(bfrag + (size_t)kc*256);
            const float4 bv1 = *(const float4*)(bfrag + (size_t)kc*256 + 4);
            s0[0] += bv0.x; s0[1] += bv0.y; s0[2] += bv0.z; s0[3] += bv0.w;
            s1[0] += bv1.x; s1[1] += bv1.y; s1[2] += bv1.z; s1[3] += bv1.w;
            float cmg = fmaxf(fmaxf(s0[0], s0[1]), fmaxf(s1[0], s1[1]));
            float cmh = fmaxf(fmaxf(s0[2], s0[3]), fmaxf(s1[2], s1[3]));
            cmg = fmaxf(cmg, __shfl_xor_sync(0xffffffffu, cmg, 1));
            cmg = fmaxf(cmg, __shfl_xor_sync(0xffffffffu, cmg, 2));
            cmh = fmaxf(cmh, __shfl_xor_sync(0xffffffffu, cmh, 1));
            cmh = fmaxf(cmh, __shfl_xor_sync(0xffffffffu, cmh, 2));
            if (__any_sync(0xffffffffu, (cmg > m_g) || (cmh > m_h))) {
                float nm_g = fmaxf(m_g, cmg), nm_h = fmaxf(m_h, cmh);
                float rg = ex2f(m_g - nm_g), rh = ex2f(m_h - nm_h);
                den_g *= rg; den_h *= rh;
                #pragma unroll
                for (int dt = 0; dt < 8; dt++) {
                    o[dt][0] *= rg; o[dt][1] *= rg;
                    o[dt][2] *= rh; o[dt][3] *= rh;
                }
                m_g = nm_g; m_h = nm_h;
            }
            float p00 = ex2f(s0[0] - m_g), p01 = ex2f(s0[1] - m_g);
            float p02 = ex2f(s0[2] - m_h), p03 = ex2f(s0[3] - m_h);
            float p10 = ex2f(s1[0] - m_g), p11 = ex2f(s1[1] - m_g);
            float p12 = ex2f(s1[2] - m_h), p13 = ex2f(s1[3] - m_h);
            den_g += (p00 + p01) + (p10 + p11);
            den_h += (p02 + p03) + (p12 + p13);
            unsigned ph[4], pl[4];
            {
                __half ha, la, hb2, lb2;
                spl(p00, ha, la); spl(p01, hb2, lb2);
                ph[0] = pack2(ha, hb2); pl[0] = pack2(la, lb2);
                spl(p02, ha, la); spl(p03, hb2, lb2);
                ph[1] = pack2(ha, hb2); pl[1] = pack2(la, lb2);
                spl(p10, ha, la); spl(p11, hb2, lb2);
                ph[2] = pack2(ha, hb2); pl[2] = pack2(la, lb2);
                spl(p12, ha, la); spl(p13, hb2, lb2);
                ph[3] = pack2(ha, hb2); pl[3] = pack2(la, lb2);
            }
            #pragma unroll
            for (int dt = 0; dt < 8; dt++) {
                unsigned vb0 = *(const unsigned*)&Vh[(dt*8+g)*VHP + k0 + 2*tg];
                unsigned vb1 = *(const unsigned*)&Vh[(dt*8+g)*VHP + k0 + 2*tg + 8];
                mmah(o[dt], ph[0], ph[1], ph[2], ph[3], vb0, vb1);
                mmah(o[dt], pl[0], pl[1], pl[2], pl[3], vb0, vb1);
            }
        }
        den_g += __shfl_xor_sync(0xffffffffu, den_g, 1);
        den_g += __shfl_xor_sync(0xffffffffu, den_g, 2);
        den_h += __shfl_xor_sync(0xffffffffu, den_h, 1);
        den_h += __shfl_xor_sync(0xffffffffu, den_h, 2);
        const float ig = 1.f / den_g, ih = 1.f / den_h;
        float* org = &g_ot[((size_t)b*NPIX + q0 + g)*DHD + h*VDIM];
        float* orh = &g_ot[((size_t)b*NPIX + q0 + g + 8)*DHD + h*VDIM];
        #pragma unroll
        for (int dt = 0; dt < 8; dt++) {
            float2 v0, v1;
            v0.x = fmaxf(o[dt][0] * ig, 0.f); v0.y = fmaxf(o[dt][1] * ig, 0.f);
            v1.x = fmaxf(o[dt][2] * ih, 0.f); v1.y = fmaxf(o[dt][3] * ih, 0.f);
            *(float2*)&org[dt*8 + 2*tg] = v0;
            *(float2*)&orh[dt*8 + 2*tg] = v1;
        }
    }
}

// ---------------- launch ----------------
extern "C" void kernel_launch(void* const* d_in, const int* in_sizes, int n_in,
                              void* d_out, int out_size) {
    const float* x      = (const float*)d_in[0];
    const float* qkv_w  = (const float*)d_in[1];
    const float* qkv_s  = (const float*)d_in[2];
    const float* qkv_b  = (const float*)d_in[3];
    const float* dw_w   = (const float*)d_in[4];
    const float* dw_s   = (const float*)d_in[5];
    const float* dw_b   = (const float*)d_in[6];
    const float* proj_w = (const float*)d_in[7];
    const float* proj_s = (const float*)d_in[8];
    const float* proj_b = (const float*)d_in[9];
    const float* ab     = (const float*)d_in[10];
    const float* pw1_w  = (const float*)d_in[11];
    const float* pw1_s  = (const float*)d_in[12];
    const float* pw1_b  = (const float*)d_in[13];
    const float* pw2_w  = (const float*)d_in[14];
    const float* pw2_s  = (const float*)d_in[15];
    const float* pw2_b  = (const float*)d_in[16];
    const int*   idxs   = (const int*)d_in[17];

    float *p_qkv, *p_ot, *p_y1, *p_hb;
    cudaGetSymbolAddress((void**)&p_qkv, g_qkv);
    cudaGetSymbolAddress((void**)&p_ot,  g_ot);
    cudaGetSymbolAddress((void**)&p_y1,  g_y1);
    cudaGetSymbolAddress((void**)&p_hb,  g_hb);

    // bias pipeline
    k_mtaps<<<1, 512>>>();
    k_bias1<<<(NHEAD*NPIX*SPIX + 255)/256, 256>>>(ab, idxs);
    k_bias2<<<(NHEAD*25*25*32*8 + 255)/256, 256>>>();

    // qkv conv1x1 (f16 mma)
    k_gemm_h<<<dim3(7, HQ/128, NB), 256>>>(x, qkv_w, qkv_s, qkv_b, nullptr, p_qkv, HQ, EDIM, 0);
    // depthwise 3x3 on q
    k_dwconv<<<(NB*128*NPIX + 255)/256, 256>>>(dw_w, dw_s, dw_b);

    // tensor-core flash attention (relu fused into output store)
    const int smem = (9600 + 9600 + VDIM*VHP) * 2;  // 90624 B
    cudaFuncSetAttribute(k_attn6, cudaFuncAttributeMaxDynamicSharedMemorySize, smem);
    k_attn6<<<NB*NHEAD, 256, smem>>>();

    // proj (X transposed [b][p][512], residual x) -> y1
    k_gemm_h<<<dim3(7, EDIM/128, NB), 256>>>(p_ot, proj_w, proj_s, proj_b, x, p_y1, EDIM, DHD, 4);
    // pw1 (relu-out) -> h
    k_gemm_h<<<dim3(7, DHD/128, NB), 256>>>(p_y1, pw1_w, pw1_s, pw1_b, nullptr, p_hb, DHD, EDIM, 2);
    // pw2 (residual y1) -> out
    k_gemm_h<<<dim3(7, EDIM/128, NB), 256>>>(p_hb, pw2_w, pw2_s, pw2_b, p_y1, (float*)d_out, EDIM, DHD, 0);
}

// round 13
// speedup vs baseline: 1.3125x; 1.1459x over previous
#include <cuda_runtime.h>
#include <cuda_fp16.h>
#include <math.h>

#define NB    32
#define EDIM  256
#define NHEAD 8
#define KDIM  16
#define VDIM  64
#define DHD   512
#define HQ    768
#define NPIX  400
#define SPIX  196
#define TSP   40    // GEMM smem tile row stride (halves); 80B = 5*16B -> cp.async-aligned,
                    // ldmatrix phases hit banks 20r mod 32 = all distinct
#define QTP   24    // Khi/Klo row stride (halves)
#define VHP   408   // Vh row stride (halves)
#define QSC   0.3606737602222409f   // 0.25 * log2(e)
#define L2E   1.4426950408889634f

typedef unsigned long long ull;

__device__ __forceinline__ float ex2f(float x) {
    float y; asm("ex2.approx.ftz.f32 %0, %1;" : "=f"(y) : "f"(x)); return y;
}
__device__ __forceinline__ void mmah(float* c, unsigned a0, unsigned a1, unsigned a2, unsigned a3,
                                     unsigned b0, unsigned b1) {
    asm volatile("mma.sync.aligned.m16n8k16.row.col.f32.f16.f16.f32 "
        "{%0,%1,%2,%3}, {%4,%5,%6,%7}, {%8,%9}, {%0,%1,%2,%3};"
        : "+f"(c[0]), "+f"(c[1]), "+f"(c[2]), "+f"(c[3])
        : "r"(a0), "r"(a1), "r"(a2), "r"(a3), "r"(b0), "r"(b1));
}
__device__ __forceinline__ void ldsm4(unsigned& r0, unsigned& r1, unsigned& r2, unsigned& r3,
                                      unsigned addr) {
    asm volatile("ldmatrix.sync.aligned.m8n8.x4.shared.b16 {%0,%1,%2,%3}, [%4];"
        : "=r"(r0), "=r"(r1), "=r"(r2), "=r"(r3) : "r"(addr));
}
__device__ __forceinline__ void spl(float x, __half& hi, __half& lo) {
    hi = __float2half(x);
    lo = __float2half(x - __half2float(hi));
}
__device__ __forceinline__ unsigned pack2(__half a, __half b) {
    return (unsigned)__half_as_ushort(a) | ((unsigned)__half_as_ushort(b) << 16);
}
__device__ __forceinline__ unsigned saddr(const void* p) {
    return (unsigned)__cvta_generic_to_shared(p);
}
__device__ __forceinline__ void cpa16(unsigned dst, const void* src, int src_bytes) {
    asm volatile("cp.async.ca.shared.global [%0], [%1], 16, %2;"
        :: "r"(dst), "l"(src), "r"(src_bytes));
}
__device__ __forceinline__ void cpa_commit() { asm volatile("cp.async.commit_group;"); }
template<int N> __device__ __forceinline__ void cpa_wait() {
    asm volatile("cp.async.wait_group %0;" :: "n"(N));
}

// ---------------- device scratch ----------------
__device__ __align__(16) float  g_qkv [NB*HQ*NPIX];
__device__ __align__(16) float  g_qdw [NB*128*NPIX];     // pre-scaled by QSC
__device__ __align__(16) float  g_tmpb[NHEAD*NPIX*SPIX];
__device__ __align__(16) float  g_bias[NHEAD*NPIX*NPIX]; // fragment layout, *L2E
__device__ __align__(16) float  g_y1  [NB*EDIM*NPIX];    // f32 proj residual output
__device__ __align__(16) __half g_xh  [NB*NPIX*EDIM];    // x transposed f16 [b][p][ci]
__device__ __align__(16) __half g_oth [NB*NPIX*DHD];     // relu(attention out) f16 [b][p][hd]
__device__ __align__(16) __half g_y1h [NB*NPIX*EDIM];    // y1 f16 [b][p][o]
__device__ __align__(16) __half g_hbh [NB*NPIX*DHD];     // relu(pw1) f16 [b][p][o]
__device__ __align__(16) __half g_whq [HQ*EDIM];
__device__ __align__(16) __half g_whp [EDIM*DHD];
__device__ __align__(16) __half g_wh1 [DHD*EDIM];
__device__ __align__(16) __half g_wh2 [EDIM*DHD];
__device__ int   g_midx[NPIX*4];
__device__ float g_mw  [NPIX*4];

// ---------------- setup converts ----------------
__global__ void k_cvtw(const float* __restrict__ src, __half* __restrict__ dst, int n4) {
    int i = blockIdx.x*blockDim.x + threadIdx.x;
    if (i >= n4) return;
    float4 v = *(const float4*)&src[i*4];
    __half h[4] = {__float2half(v.x), __float2half(v.y), __float2half(v.z), __float2half(v.w)};
    *(ull*)&dst[i*4] = *(ull*)h;
}
// xh[b][p][ci] = f16(x[b][ci][p])
__global__ void k_cvtx(const float* __restrict__ x) {
    int i = blockIdx.x*blockDim.x + threadIdx.x;
    if (i >= NB*EDIM*NPIX) return;
    int p  = i % NPIX;
    int ci = (i / NPIX) % EDIM;
    int b  = i / (EDIM*NPIX);
    g_xh[((size_t)b*NPIX + p)*EDIM + ci] = __float2half(x[i]);
}

// ---------------- bicubic taps ----------------
__global__ void k_mtaps() {
    int i = blockIdx.x*blockDim.x + threadIdx.x;
    if (i >= NPIX) return;
    double scale = (double)SPIX / (double)NPIX;
    double src = (i + 0.5)*scale - 0.5;
    double f = floor(src);
    double t = src - f;
    const double a = -0.75;
    for (int j = -1; j <= 2; j++) {
        double xx = fabs((double)j - t);
        double w;
        if (xx <= 1.0)      w = (a+2.0)*xx*xx*xx - (a+3.0)*xx*xx + 1.0;
        else if (xx < 2.0)  w = a*xx*xx*xx - 5.0*a*xx*xx + 8.0*a*xx - 4.0*a;
        else                w = 0.0;
        int idx = (int)f + j;
        idx = min(max(idx, 0), SPIX-1);
        g_midx[i*4 + (j+1)] = idx;
        g_mw  [i*4 + (j+1)] = (float)w;
    }
}

__global__ void k_bias1(const float* __restrict__ ab, const int* __restrict__ idxs) {
    int i = blockIdx.x*blockDim.x + threadIdx.x;
    if (i >= NHEAD*NPIX*SPIX) return;
    int t = i % SPIX;
    int n = (i / SPIX) % NPIX;
    int h = i / (SPIX*NPIX);
    float acc = 0.f;
    #pragma unroll
    for (int k = 0; k < 4; k++) {
        int s = g_midx[n*4+k];
        acc += g_mw[n*4+k] * ab[h*SPIX + idxs[s*SPIX + t]];
    }
    g_tmpb[i] = acc;
}

// bias in m16n8k16 C-fragment order: out[h][qt][kc][lane][j] = L2E * bias(h,q,k)
__global__ void k_bias2() {
    int i = blockIdx.x*blockDim.x + threadIdx.x;
    if (i >= NHEAD*25*25*32*8) return;
    int j    = i & 7;
    int lane = (i >> 3) & 31;
    int kc   = (i >> 8) % 25;
    int qt   = ((i >> 8) / 25) % 25;
    int h    = (i >> 8) / 625;
    int g = lane >> 2, tg = lane & 3;
    int dr = ((j >> 1) & 1) * 8;
    int dc = 2*tg + (j & 1) + ((j >= 4) ? 8 : 0);
    int q = qt*16 + g + dr;
    int k = kc*16 + dc;
    const float* trow = g_tmpb + ((size_t)h*NPIX + q)*SPIX;
    float acc = 0.f;
    #pragma unroll
    for (int kk = 0; kk < 4; kk++)
        acc += g_mw[k*4+kk] * trow[g_midx[k*4+kk]];
    g_bias[i] = acc * L2E;
}

// ---------------- depthwise 3x3 (output pre-scaled by QSC) ----------------
__global__ void k_dwconv(const float* __restrict__ w, const float* __restrict__ s,
                         const float* __restrict__ bia) {
    int i = blockIdx.x*blockDim.x + threadIdx.x;
    if (i >= NB*128*NPIX) return;
    int p = i % NPIX;
    int c = (i / NPIX) % 128;
    int b = i / (128*NPIX);
    int y = p / 20, x = p % 20;
    const float* src = g_qkv + ((size_t)b*HQ + c)*NPIX;
    float acc = 0.f;
    #pragma unroll
    for (int dy = -1; dy <= 1; dy++) {
        int yy = y + dy;
        if (yy < 0 || yy >= 20) continue;
        #pragma unroll
        for (int dx = -1; dx <= 1; dx++) {
            int xx = x + dx;
            if (xx < 0 || xx >= 20) continue;
            acc += w[c*9 + (dy+1)*3 + (dx+1)] * src[yy*20 + xx];
        }
    }
    g_qdw[i] = (acc * s[c] + bia[c]) * QSC;
}

// ---------------- all-f16 GEMM: cp.async double-buffer + ldmatrix ----------------
// W f16 [O][Cin] row-major; X f16 [b][p][Cin] (k contiguous).
// Smem tiles: Ws [128 o][TSP], Xs [64 p][TSP]. CTA 128x64, 8 warps 4x2.
// Outputs: Yf (f32 [b][O][p], optional, +R residual) and/or Yh (f16 [b][p][O], scatter).
__global__ void __launch_bounds__(256, 3) k_gemm_f(
    const __half* __restrict__ X, const __half* __restrict__ W,
    const float* __restrict__ sc, const float* __restrict__ bi,
    const float* __restrict__ R, float* __restrict__ Yf, __half* __restrict__ Yh,
    int O, int Cin, int relu)
{
    __shared__ __align__(16) __half Ws[2][128*TSP];
    __shared__ __align__(16) __half Xs[2][64*TSP];
    const int b  = blockIdx.z;
    const int oT = blockIdx.y * 128;
    const int pT = blockIdx.x * 64;
    const int t  = threadIdx.x;
    const int wid = t >> 5, lane = t & 31;
    const int g = lane >> 2, tg = lane & 3;
    const int warpM = wid & 3, warpN = wid >> 2;

    float acc[2][4][4];
    #pragma unroll
    for (int mt = 0; mt < 2; mt++)
        #pragma unroll
        for (int nt = 0; nt < 4; nt++)
            #pragma unroll
            for (int i = 0; i < 4; i++) acc[mt][nt][i] = 0.f;

    const int nchunk = Cin >> 5;

    // copy coordinates (fixed): W 2x16B/thread, X 1x16B/thread
    const int wRow0 = t >> 2, wSeg0 = (t & 3) * 8;        // rows 0..63
    const int wRow1 = wRow0 + 64;                          // rows 64..127
    const int xRow  = t >> 2, xSeg = (t & 3) * 8;          // rows 0..63
    const int xP    = pT + xRow;
    const __half* Wb0 = &W[(size_t)(oT + wRow0)*Cin + wSeg0];
    const __half* Wb1 = &W[(size_t)(oT + wRow1)*Cin + wSeg0];
    const __half* Xb  = &X[((size_t)b*NPIX + xP)*Cin + xSeg];
    const int xBytes = (xP < NPIX) ? 16 : 0;

    #define COPY_CHUNK(k0, buf)                                          \
    {                                                                    \
        cpa16(saddr(&Ws[buf][wRow0*TSP + wSeg0]), Wb0 + (k0), 16);       \
        cpa16(saddr(&Ws[buf][wRow1*TSP + wSeg0]), Wb1 + (k0), 16);       \
        cpa16(saddr(&Xs[buf][xRow*TSP + xSeg]),  Xb  + (k0), xBytes);    \
        cpa_commit();                                                    \
    }

    COPY_CHUNK(0, 0);

    // ldmatrix lane addressing
    const int rA = (lane & 7) + ((lane >> 3) & 1) * 8;
    const int cA = ((lane >> 4) & 1) * 8;
    const int rB = (lane & 7) + ((lane >> 4) & 1) * 8;
    const int cB = ((lane >> 3) & 1) * 8;

    for (int c = 0; c < nchunk; c++) {
        const int buf = c & 1;
        if (c + 1 < nchunk) {
            COPY_CHUNK((c+1)*32, (c+1) & 1);
            cpa_wait<1>();
        } else {
            cpa_wait<0>();
        }
        __syncthreads();

        #pragma unroll
        for (int ks = 0; ks < 2; ks++) {
            const int kk = ks * 16;
            unsigned a[2][4], bm[2][4];
            #pragma unroll
            for (int mt = 0; mt < 2; mt++)
                ldsm4(a[mt][0], a[mt][1], a[mt][2], a[mt][3],
                      saddr(&Ws[buf][(warpM*32 + mt*16 + rA)*TSP + kk + cA]));
            #pragma unroll
            for (int ntp = 0; ntp < 2; ntp++)
                ldsm4(bm[ntp][0], bm[ntp][1], bm[ntp][2], bm[ntp][3],
                      saddr(&Xs[buf][(warpN*32 + ntp*16 + rB)*TSP + kk + cB]));
            #pragma unroll
            for (int mt = 0; mt < 2; mt++)
                #pragma unroll
                for (int ntp = 0; ntp < 2; ntp++) {
                    mmah(acc[mt][2*ntp],   a[mt][0], a[mt][1], a[mt][2], a[mt][3],
                         bm[ntp][0], bm[ntp][1]);
                    mmah(acc[mt][2*ntp+1], a[mt][0], a[mt][1], a[mt][2], a[mt][3],
                         bm[ntp][2], bm[ntp][3]);
                }
        }
        __syncthreads();
    }
    #undef COPY_CHUNK

    // ---- epilogue ----
    #pragma unroll
    for (int mt = 0; mt < 2; mt++) {
        const int o0 = oT + warpM*32 + mt*16 + g;
        const int o1 = o0 + 8;
        const float s0 = sc[o0], bb0 = bi[o0];
        const float s1 = sc[o1], bb1 = bi[o1];
        #pragma unroll
        for (int nt = 0; nt < 4; nt++) {
            const int p = pT + warpN*32 + nt*8 + 2*tg;
            if (p < NPIX) {
                float2 v0, v1;
                v0.x = acc[mt][nt][0]*s0 + bb0;
                v0.y = acc[mt][nt][1]*s0 + bb0;
                v1.x = acc[mt][nt][2]*s1 + bb1;
                v1.y = acc[mt][nt][3]*s1 + bb1;
                const size_t off0 = ((size_t)b*O + o0)*NPIX + p;
                const size_t off1 = ((size_t)b*O + o1)*NPIX + p;
                if (R) {
                    float2 r0 = *(const float2*)&R[off0];
                    float2 r1 = *(const float2*)&R[off1];
                    v0.x += r0.x; v0.y += r0.y;
                    v1.x += r1.x; v1.y += r1.y;
                }
                if (relu) {
                    v0.x = fmaxf(v0.x,0.f); v0.y = fmaxf(v0.y,0.f);
                    v1.x = fmaxf(v1.x,0.f); v1.y = fmaxf(v1.y,0.f);
                }
                if (Yf) {
                    *(float2*)&Yf[off0] = v0;
                    *(float2*)&Yf[off1] = v1;
                }
                if (Yh) {
                    __half* yr0 = &Yh[((size_t)b*NPIX + p)*O];
                    __half* yr1 = yr0 + O;
                    yr0[o0] = __float2half(v0.x);
                    yr1[o0] = __float2half(v0.y);
                    yr0[o1] = __float2half(v1.x);
                    yr1[o1] = __float2half(v1.y);
                }
            }
        }
    }
}

// ---------------- tensor-core flash attention, split-f16 ----------------
// Output: g_oth f16 [b][p][hd], relu fused (feeds proj GEMM directly).
__global__ void __launch_bounds__(256, 2) k_attn6() {
    extern __shared__ __half smh[];
    __half* Khi = smh;              // [400][QTP]
    __half* Klo = smh + 9600;       // [400][QTP]
    __half* Vh  = smh + 19200;      // [64][VHP]
    const int bh = blockIdx.x;
    const int b = bh >> 3, h = bh & 7;
    const int tid = threadIdx.x;

    const float* qb = g_qdw + ((size_t)b*128 + h*KDIM)*NPIX;
    const float* kb = g_qkv + ((size_t)b*HQ + 128 + h*KDIM)*NPIX;
    const float* vb = g_qkv + ((size_t)b*HQ + 256 + h*VDIM)*NPIX;

    for (int i = tid; i < KDIM*NPIX; i += 256) {
        int d = i / NPIX, p = i - d*NPIX;
        __half hi, lo; spl(kb[i], hi, lo);
        Khi[p*QTP + d] = hi;
        Klo[p*QTP + d] = lo;
    }
    for (int i = tid; i < VDIM*NPIX; i += 256) {
        int d = i / NPIX, p = i - d*NPIX;
        Vh[d*VHP + p] = __float2half(vb[i]);
    }
    __syncthreads();

    const int w = tid >> 5, lane = tid & 31;
    const int g = lane >> 2, tg = lane & 3;

    for (int tile = w; tile < 25; tile += 8) {
        const int q0 = tile * 16;
        unsigned qh[4], ql[4];
        {
            const int r0 = q0 + g, r1 = q0 + g + 8;
            const int d0 = 2*tg, d1 = 2*tg + 8;
            float q00a = qb[(d0  )*NPIX + r0], q00b = qb[(d0+1)*NPIX + r0];
            float q10a = qb[(d0  )*NPIX + r1], q10b = qb[(d0+1)*NPIX + r1];
            float q01a = qb[(d1  )*NPIX + r0], q01b = qb[(d1+1)*NPIX + r0];
            float q11a = qb[(d1  )*NPIX + r1], q11b = qb[(d1+1)*NPIX + r1];
            __half ha, la, hb2, lb2;
            spl(q00a, ha, la); spl(q00b, hb2, lb2);
            qh[0] = pack2(ha, hb2); ql[0] = pack2(la, lb2);
            spl(q10a, ha, la); spl(q10b, hb2, lb2);
            qh[1] = pack2(ha, hb2); ql[1] = pack2(la, lb2);
            spl(q01a, ha, la); spl(q01b, hb2, lb2);
            qh[2] = pack2(ha, hb2); ql[2] = pack2(la, lb2);
            spl(q11a, ha, la); spl(q11b, hb2, lb2);
            qh[3] = pack2(ha, hb2); ql[3] = pack2(la, lb2);
        }

        float o[8][4];
        #pragma unroll
        for (int dt = 0; dt < 8; dt++)
            #pragma unroll
            for (int i = 0; i < 4; i++) o[dt][i] = 0.f;
        float m_g = -1e30f, m_h = -1e30f, den_g = 0.f, den_h = 0.f;

        const float* bfrag = &g_bias[((((size_t)h*25 + tile)*25)*32 + lane)*8];

        for (int kc = 0; kc < 25; kc++) {
            const int k0 = kc * 16;
            float s0[4] = {0.f,0.f,0.f,0.f};
            float s1[4] = {0.f,0.f,0.f,0.f};
            {
                unsigned b0h = *(const unsigned*)&Khi[(k0+g)*QTP + 2*tg];
                unsigned b1h = *(const unsigned*)&Khi[(k0+g)*QTP + 2*tg + 8];
                unsigned b0l = *(const unsigned*)&Klo[(k0+g)*QTP + 2*tg];
                unsigned b1l = *(const unsigned*)&Klo[(k0+g)*QTP + 2*tg + 8];
                mmah(s0, qh[0], qh[1], qh[2], qh[3], b0h, b1h);
                mmah(s0, qh[0], qh[1], qh[2], qh[3], b0l, b1l);
                mmah(s0, ql[0], ql[1], ql[2], ql[3], b0h, b1h);
                unsigned c0h = *(const unsigned*)&Khi[(k0+8+g)*QTP + 2*tg];
                unsigned c1h = *(const unsigned*)&Khi[(k0+8+g)*QTP + 2*tg + 8];
                unsigned c0l = *(const unsigned*)&Klo[(k0+8+g)*QTP + 2*tg];
                unsigned c1l = *(const unsigned*)&Klo[(k0+8+g)*QTP + 2*tg + 8];
                mmah(s1, qh[0], qh[1], qh[2], qh[3], c0h, c1h);
                mmah(s1, qh[0], qh[1], qh[2], qh[3], c0l, c1l);
                mmah(s1, ql[0], ql[1], ql[2], ql[3], c0h, c1h);
            }
            const float4 bv0 = *(const float4*)(bfrag + (size_t)kc*256);
            const float4 bv1 = *(const float4*)(bfrag + (size_t)kc*256 + 4);
            s0[0] += bv0.x; s0[1] += bv0.y; s0[2] += bv0.z; s0[3] += bv0.w;
            s1[0] += bv1.x; s1[1] += bv1.y; s1[2] += bv1.z; s1[3] += bv1.w;
            float cmg = fmaxf(fmaxf(s0[0], s0[1]), fmaxf(s1[0], s1[1]));
            float cmh = fmaxf(fmaxf(s0[2], s0[3]), fmaxf(s1[2], s1[3]));
            cmg = fmaxf(cmg, __shfl_xor_sync(0xffffffffu, cmg, 1));
            cmg = fmaxf(cmg, __shfl_xor_sync(0xffffffffu, cmg, 2));
            cmh = fmaxf(cmh, __shfl_xor_sync(0xffffffffu, cmh, 1));
            cmh = fmaxf(cmh, __shfl_xor_sync(0xffffffffu, cmh, 2));
            if (__any_sync(0xffffffffu, (cmg > m_g) || (cmh > m_h))) {
                float nm_g = fmaxf(m_g, cmg), nm_h = fmaxf(m_h, cmh);
                float rg = ex2f(m_g - nm_g), rh = ex2f(m_h - nm_h);
                den_g *= rg; den_h *= rh;
                #pragma unroll
                for (int dt = 0; dt < 8; dt++) {
                    o[dt][0] *= rg; o[dt][1] *= rg;
                    o[dt][2] *= rh; o[dt][3] *= rh;
                }
                m_g = nm_g; m_h = nm_h;
            }
            float p00 = ex2f(s0[0] - m_g), p01 = ex2f(s0[1] - m_g);
            float p02 = ex2f(s0[2] - m_h), p03 = ex2f(s0[3] - m_h);
            float p10 = ex2f(s1[0] - m_g), p11 = ex2f(s1[1] - m_g);
            float p12 = ex2f(s1[2] - m_h), p13 = ex2f(s1[3] - m_h);
            den_g += (p00 + p01) + (p10 + p11);
            den_h += (p02 + p03) + (p12 + p13);
            unsigned ph[4], pl[4];
            {
                __half ha, la, hb2, lb2;
                spl(p00, ha, la); spl(p01, hb2, lb2);
                ph[0] = pack2(ha, hb2); pl[0] = pack2(la, lb2);
                spl(p02, ha, la); spl(p03, hb2, lb2);
                ph[1] = pack2(ha, hb2); pl[1] = pack2(la, lb2);
                spl(p10, ha, la); spl(p11, hb2, lb2);
                ph[2] = pack2(ha, hb2); pl[2] = pack2(la, lb2);
                spl(p12, ha, la); spl(p13, hb2, lb2);
                ph[3] = pack2(ha, hb2); pl[3] = pack2(la, lb2);
            }
            #pragma unroll
            for (int dt = 0; dt < 8; dt++) {
                unsigned vb0 = *(const unsigned*)&Vh[(dt*8+g)*VHP + k0 + 2*tg];
                unsigned vb1 = *(const unsigned*)&Vh[(dt*8+g)*VHP + k0 + 2*tg + 8];
                mmah(o[dt], ph[0], ph[1], ph[2], ph[3], vb0, vb1);
                mmah(o[dt], pl[0], pl[1], pl[2], pl[3], vb0, vb1);
            }
        }
        den_g += __shfl_xor_sync(0xffffffffu, den_g, 1);
        den_g += __shfl_xor_sync(0xffffffffu, den_g, 2);
        den_h += __shfl_xor_sync(0xffffffffu, den_h, 1);
        den_h += __shfl_xor_sync(0xffffffffu, den_h, 2);
        const float ig = 1.f / den_g, ih = 1.f / den_h;
        __half* org = &g_oth[((size_t)b*NPIX + q0 + g)*DHD + h*VDIM];
        __half* orh = &g_oth[((size_t)b*NPIX + q0 + g + 8)*DHD + h*VDIM];
        #pragma unroll
        for (int dt = 0; dt < 8; dt++) {
            float v0x = fmaxf(o[dt][0] * ig, 0.f), v0y = fmaxf(o[dt][1] * ig, 0.f);
            float v1x = fmaxf(o[dt][2] * ih, 0.f), v1y = fmaxf(o[dt][3] * ih, 0.f);
            *(__half2*)&org[dt*8 + 2*tg] = __floats2half2_rn(v0x, v0y);
            *(__half2*)&orh[dt*8 + 2*tg] = __floats2half2_rn(v1x, v1y);
        }
    }
}

// ---------------- launch ----------------
extern "C" void kernel_launch(void* const* d_in, const int* in_sizes, int n_in,
                              void* d_out, int out_size) {
    const float* x      = (const float*)d_in[0];
    const float* qkv_w  = (const float*)d_in[1];
    const float* qkv_s  = (const float*)d_in[2];
    const float* qkv_b  = (const float*)d_in[3];
    const float* dw_w   = (const float*)d_in[4];
    const float* dw_s   = (const float*)d_in[5];
    const float* dw_b   = (const float*)d_in[6];
    const float* proj_w = (const float*)d_in[7];
    const float* proj_s = (const float*)d_in[8];
    const float* proj_b = (const float*)d_in[9];
    const float* ab     = (const float*)d_in[10];
    const float* pw1_w  = (const float*)d_in[11];
    const float* pw1_s  = (const float*)d_in[12];
    const float* pw1_b  = (const float*)d_in[13];
    const float* pw2_w  = (const float*)d_in[14];
    const float* pw2_s  = (const float*)d_in[15];
    const float* pw2_b  = (const float*)d_in[16];
    const int*   idxs   = (const int*)d_in[17];

    float *p_qkv, *p_y1;
    __half *p_xh, *p_oth, *p_y1h, *p_hbh, *p_whq, *p_whp, *p_wh1, *p_wh2;
    cudaGetSymbolAddress((void**)&p_qkv, g_qkv);
    cudaGetSymbolAddress((void**)&p_y1,  g_y1);
    cudaGetSymbolAddress((void**)&p_xh,  g_xh);
    cudaGetSymbolAddress((void**)&p_oth, g_oth);
    cudaGetSymbolAddress((void**)&p_y1h, g_y1h);
    cudaGetSymbolAddress((void**)&p_hbh, g_hbh);
    cudaGetSymbolAddress((void**)&p_whq, g_whq);
    cudaGetSymbolAddress((void**)&p_whp, g_whp);
    cudaGetSymbolAddress((void**)&p_wh1, g_wh1);
    cudaGetSymbolAddress((void**)&p_wh2, g_wh2);

    // setup converts
    k_cvtw<<<(HQ*EDIM/4 + 255)/256, 256>>>(qkv_w,  p_whq, HQ*EDIM/4);
    k_cvtw<<<(EDIM*DHD/4 + 255)/256, 256>>>(proj_w, p_whp, EDIM*DHD/4);
    k_cvtw<<<(DHD*EDIM/4 + 255)/256, 256>>>(pw1_w,  p_wh1, DHD*EDIM/4);
    k_cvtw<<<(EDIM*DHD/4 + 255)/256, 256>>>(pw2_w,  p_wh2, EDIM*DHD/4);
    k_cvtx<<<(NB*EDIM*NPIX + 255)/256, 256>>>(x);

    // bias pipeline
    k_mtaps<<<1, 512>>>();
    k_bias1<<<(NHEAD*NPIX*SPIX + 255)/256, 256>>>(ab, idxs);
    k_bias2<<<(NHEAD*25*25*32*8 + 255)/256, 256>>>();

    // qkv conv1x1
    k_gemm_f<<<dim3(7, HQ/128, NB), 256>>>(p_xh, p_whq, qkv_s, qkv_b,
                                           nullptr, p_qkv, nullptr, HQ, EDIM, 0);
    // depthwise 3x3 on q
    k_dwconv<<<(NB*128*NPIX + 255)/256, 256>>>(dw_w, dw_s, dw_b);

    // tensor-core flash attention (f16 + relu output)
    const int smem = (9600 + 9600 + VDIM*VHP) * 2;  // 90624 B
    cudaFuncSetAttribute(k_attn6, cudaFuncAttributeMaxDynamicSharedMemorySize, smem);
    k_attn6<<<NB*NHEAD, 256, smem>>>();

    // proj (+x residual) -> y1 f32 + y1h f16
    k_gemm_f<<<dim3(7, EDIM/128, NB), 256>>>(p_oth, p_whp, proj_s, proj_b,
                                             x, p_y1, p_y1h, EDIM, DHD, 0);
    // pw1 (relu) -> hbh f16 only
    k_gemm_f<<<dim3(7, DHD/128, NB), 256>>>(p_y1h, p_wh1, pw1_s, pw1_b,
                                            nullptr, nullptr, p_hbh, DHD, EDIM, 1);
    // pw2 (+y1 residual) -> out f32
    k_gemm_f<<<dim3(7, EDIM/128, NB), 256>>>(p_hbh, p_wh2, pw2_s, pw2_b,
                                             p_y1, (float*)d_out, nullptr, EDIM, DHD, 0);
}

// round 14
// speedup vs baseline: 1.3767x; 1.0489x over previous
#include <cuda_runtime.h>
#include <cuda_fp16.h>
#include <math.h>

#define NB    32
#define EDIM  256
#define NHEAD 8
#define KDIM  16
#define VDIM  64
#define DHD   512
#define HQ    768
#define NPIX  400
#define SPIX  196
#define TSP   40    // GEMM smem tile row stride (halves)
#define QTP   24    // Khi/Klo row stride (halves)
#define VHP   408   // Vh row stride (halves)
#define QSC   0.3606737602222409f   // 0.25 * log2(e)
#define L2E   1.4426950408889634f

typedef unsigned long long ull;

__device__ __forceinline__ float ex2f(float x) {
    float y; asm("ex2.approx.ftz.f32 %0, %1;" : "=f"(y) : "f"(x)); return y;
}
__device__ __forceinline__ void mmah(float* c, unsigned a0, unsigned a1, unsigned a2, unsigned a3,
                                     unsigned b0, unsigned b1) {
    asm volatile("mma.sync.aligned.m16n8k16.row.col.f32.f16.f16.f32 "
        "{%0,%1,%2,%3}, {%4,%5,%6,%7}, {%8,%9}, {%0,%1,%2,%3};"
        : "+f"(c[0]), "+f"(c[1]), "+f"(c[2]), "+f"(c[3])
        : "r"(a0), "r"(a1), "r"(a2), "r"(a3), "r"(b0), "r"(b1));
}
__device__ __forceinline__ void ldsm4(unsigned& r0, unsigned& r1, unsigned& r2, unsigned& r3,
                                      unsigned addr) {
    asm volatile("ldmatrix.sync.aligned.m8n8.x4.shared.b16 {%0,%1,%2,%3}, [%4];"
        : "=r"(r0), "=r"(r1), "=r"(r2), "=r"(r3) : "r"(addr));
}
__device__ __forceinline__ void spl(float x, __half& hi, __half& lo) {
    hi = __float2half(x);
    lo = __float2half(x - __half2float(hi));
}
__device__ __forceinline__ unsigned pack2(__half a, __half b) {
    return (unsigned)__half_as_ushort(a) | ((unsigned)__half_as_ushort(b) << 16);
}
__device__ __forceinline__ unsigned saddr(const void* p) {
    return (unsigned)__cvta_generic_to_shared(p);
}
__device__ __forceinline__ void cpa16(unsigned dst, const void* src, int src_bytes) {
    asm volatile("cp.async.ca.shared.global [%0], [%1], 16, %2;"
        :: "r"(dst), "l"(src), "r"(src_bytes));
}
__device__ __forceinline__ void cpa_commit() { asm volatile("cp.async.commit_group;"); }
template<int N> __device__ __forceinline__ void cpa_wait() {
    asm volatile("cp.async.wait_group %0;" :: "n"(N));
}

// ---------------- device scratch ----------------
__device__ __align__(16) float  g_qkv [NB*HQ*NPIX];
__device__ __align__(16) float  g_qdw [NB*128*NPIX];     // pre-scaled by QSC
__device__ __align__(16) float  g_tmpb[NHEAD*NPIX*SPIX];
__device__ __align__(16) float  g_bias[NHEAD*NPIX*NPIX]; // fragment layout, *L2E
__device__ __align__(16) float  g_y1  [NB*EDIM*NPIX];    // f32 proj residual output
__device__ __align__(16) __half g_xh  [NB*NPIX*EDIM];    // x transposed f16 [b][p][ci]
__device__ __align__(16) __half g_oth [NB*NPIX*DHD];     // relu(attention out) f16 [b][p][hd]
__device__ __align__(16) __half g_y1h [NB*NPIX*EDIM];    // y1 f16 [b][p][o]
__device__ __align__(16) __half g_hbh [NB*NPIX*DHD];     // relu(pw1) f16 [b][p][o]
__device__ __align__(16) __half g_whq [HQ*EDIM];
__device__ __align__(16) __half g_whp [EDIM*DHD];
__device__ __align__(16) __half g_wh1 [DHD*EDIM];
__device__ __align__(16) __half g_wh2 [EDIM*DHD];
__device__ int   g_midx[NPIX*4];
__device__ float g_mw  [NPIX*4];

// ---------------- setup converts ----------------
__global__ void k_cvtw(const float* __restrict__ src, __half* __restrict__ dst, int n4) {
    int i = blockIdx.x*blockDim.x + threadIdx.x;
    if (i >= n4) return;
    float4 v = *(const float4*)&src[i*4];
    __half h[4] = {__float2half(v.x), __float2half(v.y), __float2half(v.z), __float2half(v.w)};
    *(ull*)&dst[i*4] = *(ull*)h;
}
// xh[b][p][ci] = f16(x[b][ci][p])
__global__ void k_cvtx(const float* __restrict__ x) {
    int i = blockIdx.x*blockDim.x + threadIdx.x;
    if (i >= NB*EDIM*NPIX) return;
    int p  = i % NPIX;
    int ci = (i / NPIX) % EDIM;
    int b  = i / (EDIM*NPIX);
    g_xh[((size_t)b*NPIX + p)*EDIM + ci] = __float2half(x[i]);
}

// ---------------- bicubic taps ----------------
__global__ void k_mtaps() {
    int i = blockIdx.x*blockDim.x + threadIdx.x;
    if (i >= NPIX) return;
    double scale = (double)SPIX / (double)NPIX;
    double src = (i + 0.5)*scale - 0.5;
    double f = floor(src);
    double t = src - f;
    const double a = -0.75;
    for (int j = -1; j <= 2; j++) {
        double xx = fabs((double)j - t);
        double w;
        if (xx <= 1.0)      w = (a+2.0)*xx*xx*xx - (a+3.0)*xx*xx + 1.0;
        else if (xx < 2.0)  w = a*xx*xx*xx - 5.0*a*xx*xx + 8.0*a*xx - 4.0*a;
        else                w = 0.0;
        int idx = (int)f + j;
        idx = min(max(idx, 0), SPIX-1);
        g_midx[i*4 + (j+1)] = idx;
        g_mw  [i*4 + (j+1)] = (float)w;
    }
}

__global__ void k_bias1(const float* __restrict__ ab, const int* __restrict__ idxs) {
    int i = blockIdx.x*blockDim.x + threadIdx.x;
    if (i >= NHEAD*NPIX*SPIX) return;
    int t = i % SPIX;
    int n = (i / SPIX) % NPIX;
    int h = i / (SPIX*NPIX);
    float acc = 0.f;
    #pragma unroll
    for (int k = 0; k < 4; k++) {
        int s = g_midx[n*4+k];
        acc += g_mw[n*4+k] * ab[h*SPIX + idxs[s*SPIX + t]];
    }
    g_tmpb[i] = acc;
}

// bias in m16n8k16 C-fragment order: out[h][qt][kc][lane][j] = L2E * bias(h,q,k)
__global__ void k_bias2() {
    int i = blockIdx.x*blockDim.x + threadIdx.x;
    if (i >= NHEAD*25*25*32*8) return;
    int j    = i & 7;
    int lane = (i >> 3) & 31;
    int kc   = (i >> 8) % 25;
    int qt   = ((i >> 8) / 25) % 25;
    int h    = (i >> 8) / 625;
    int g = lane >> 2, tg = lane & 3;
    int dr = ((j >> 1) & 1) * 8;
    int dc = 2*tg + (j & 1) + ((j >= 4) ? 8 : 0);
    int q = qt*16 + g + dr;
    int k = kc*16 + dc;
    const float* trow = g_tmpb + ((size_t)h*NPIX + q)*SPIX;
    float acc = 0.f;
    #pragma unroll
    for (int kk = 0; kk < 4; kk++)
        acc += g_mw[k*4+kk] * trow[g_midx[k*4+kk]];
    g_bias[i] = acc * L2E;
}

// ---------------- depthwise 3x3 (output pre-scaled by QSC) ----------------
__global__ void k_dwconv(const float* __restrict__ w, const float* __restrict__ s,
                         const float* __restrict__ bia) {
    int i = blockIdx.x*blockDim.x + threadIdx.x;
    if (i >= NB*128*NPIX) return;
    int p = i % NPIX;
    int c = (i / NPIX) % 128;
    int b = i / (128*NPIX);
    int y = p / 20, x = p % 20;
    const float* src = g_qkv + ((size_t)b*HQ + c)*NPIX;
    float acc = 0.f;
    #pragma unroll
    for (int dy = -1; dy <= 1; dy++) {
        int yy = y + dy;
        if (yy < 0 || yy >= 20) continue;
        #pragma unroll
        for (int dx = -1; dx <= 1; dx++) {
            int xx = x + dx;
            if (xx < 0 || xx >= 20) continue;
            acc += w[c*9 + (dy+1)*3 + (dx+1)] * src[yy*20 + xx];
        }
    }
    g_qdw[i] = (acc * s[c] + bia[c]) * QSC;
}

// ---------------- all-f16 GEMM: cp.async double-buffer + ldmatrix ----------------
__global__ void __launch_bounds__(256, 3) k_gemm_f(
    const __half* __restrict__ X, const __half* __restrict__ W,
    const float* __restrict__ sc, const float* __restrict__ bi,
    const float* __restrict__ R, float* __restrict__ Yf, __half* __restrict__ Yh,
    int O, int Cin, int relu)
{
    __shared__ __align__(16) __half Ws[2][128*TSP];
    __shared__ __align__(16) __half Xs[2][64*TSP];
    const int b  = blockIdx.z;
    const int oT = blockIdx.y * 128;
    const int pT = blockIdx.x * 64;
    const int t  = threadIdx.x;
    const int wid = t >> 5, lane = t & 31;
    const int g = lane >> 2, tg = lane & 3;
    const int warpM = wid & 3, warpN = wid >> 2;

    float acc[2][4][4];
    #pragma unroll
    for (int mt = 0; mt < 2; mt++)
        #pragma unroll
        for (int nt = 0; nt < 4; nt++)
            #pragma unroll
            for (int i = 0; i < 4; i++) acc[mt][nt][i] = 0.f;

    const int nchunk = Cin >> 5;

    const int wRow0 = t >> 2, wSeg0 = (t & 3) * 8;
    const int wRow1 = wRow0 + 64;
    const int xRow  = t >> 2, xSeg = (t & 3) * 8;
    const int xP    = pT + xRow;
    const __half* Wb0 = &W[(size_t)(oT + wRow0)*Cin + wSeg0];
    const __half* Wb1 = &W[(size_t)(oT + wRow1)*Cin + wSeg0];
    const __half* Xb  = &X[((size_t)b*NPIX + xP)*Cin + xSeg];
    const int xBytes = (xP < NPIX) ? 16 : 0;

    #define COPY_CHUNK(k0, buf)                                          \
    {                                                                    \
        cpa16(saddr(&Ws[buf][wRow0*TSP + wSeg0]), Wb0 + (k0), 16);       \
        cpa16(saddr(&Ws[buf][wRow1*TSP + wSeg0]), Wb1 + (k0), 16);       \
        cpa16(saddr(&Xs[buf][xRow*TSP + xSeg]),  Xb  + (k0), xBytes);    \
        cpa_commit();                                                    \
    }

    COPY_CHUNK(0, 0);

    const int rA = (lane & 7) + ((lane >> 3) & 1) * 8;
    const int cA = ((lane >> 4) & 1) * 8;
    const int rB = (lane & 7) + ((lane >> 4) & 1) * 8;
    const int cB = ((lane >> 3) & 1) * 8;

    for (int c = 0; c < nchunk; c++) {
        const int buf = c & 1;
        if (c + 1 < nchunk) {
            COPY_CHUNK((c+1)*32, (c+1) & 1);
            cpa_wait<1>();
        } else {
            cpa_wait<0>();
        }
        __syncthreads();

        #pragma unroll
        for (int ks = 0; ks < 2; ks++) {
            const int kk = ks * 16;
            unsigned a[2][4], bm[2][4];
            #pragma unroll
            for (int mt = 0; mt < 2; mt++)
                ldsm4(a[mt][0], a[mt][1], a[mt][2], a[mt][3],
                      saddr(&Ws[buf][(warpM*32 + mt*16 + rA)*TSP + kk + cA]));
            #pragma unroll
            for (int ntp = 0; ntp < 2; ntp++)
                ldsm4(bm[ntp][0], bm[ntp][1], bm[ntp][2], bm[ntp][3],
                      saddr(&Xs[buf][(warpN*32 + ntp*16 + rB)*TSP + kk + cB]));
            #pragma unroll
            for (int mt = 0; mt < 2; mt++)
                #pragma unroll
                for (int ntp = 0; ntp < 2; ntp++) {
                    mmah(acc[mt][2*ntp],   a[mt][0], a[mt][1], a[mt][2], a[mt][3],
                         bm[ntp][0], bm[ntp][1]);
                    mmah(acc[mt][2*ntp+1], a[mt][0], a[mt][1], a[mt][2], a[mt][3],
                         bm[ntp][2], bm[ntp][3]);
                }
        }
        __syncthreads();
    }
    #undef COPY_CHUNK

    #pragma unroll
    for (int mt = 0; mt < 2; mt++) {
        const int o0 = oT + warpM*32 + mt*16 + g;
        const int o1 = o0 + 8;
        const float s0 = sc[o0], bb0 = bi[o0];
        const float s1 = sc[o1], bb1 = bi[o1];
        #pragma unroll
        for (int nt = 0; nt < 4; nt++) {
            const int p = pT + warpN*32 + nt*8 + 2*tg;
            if (p < NPIX) {
                float2 v0, v1;
                v0.x = acc[mt][nt][0]*s0 + bb0;
                v0.y = acc[mt][nt][1]*s0 + bb0;
                v1.x = acc[mt][nt][2]*s1 + bb1;
                v1.y = acc[mt][nt][3]*s1 + bb1;
                const size_t off0 = ((size_t)b*O + o0)*NPIX + p;
                const size_t off1 = ((size_t)b*O + o1)*NPIX + p;
                if (R) {
                    float2 r0 = *(const float2*)&R[off0];
                    float2 r1 = *(const float2*)&R[off1];
                    v0.x += r0.x; v0.y += r0.y;
                    v1.x += r1.x; v1.y += r1.y;
                }
                if (relu) {
                    v0.x = fmaxf(v0.x,0.f); v0.y = fmaxf(v0.y,0.f);
                    v1.x = fmaxf(v1.x,0.f); v1.y = fmaxf(v1.y,0.f);
                }
                if (Yf) {
                    *(float2*)&Yf[off0] = v0;
                    *(float2*)&Yf[off1] = v1;
                }
                if (Yh) {
                    __half* yr0 = &Yh[((size_t)b*NPIX + p)*O];
                    __half* yr1 = yr0 + O;
                    yr0[o0] = __float2half(v0.x);
                    yr1[o0] = __float2half(v0.y);
                    yr0[o1] = __float2half(v1.x);
                    yr1[o1] = __float2half(v1.y);
                }
            }
        }
    }
}

// ---------------- tensor-core flash attention, split-f16 ----------------
__global__ void __launch_bounds__(256, 2) k_attn6() {
    extern __shared__ __half smh[];
    __half* Khi = smh;              // [400][QTP]
    __half* Klo = smh + 9600;       // [400][QTP]
    __half* Vh  = smh + 19200;      // [64][VHP]
    const int bh = blockIdx.x;
    const int b = bh >> 3, h = bh & 7;
    const int tid = threadIdx.x;

    const float* qb = g_qdw + ((size_t)b*128 + h*KDIM)*NPIX;
    const float* kb = g_qkv + ((size_t)b*HQ + 128 + h*KDIM)*NPIX;
    const float* vb = g_qkv + ((size_t)b*HQ + 256 + h*VDIM)*NPIX;

    for (int i = tid; i < KDIM*NPIX; i += 256) {
        int d = i / NPIX, p = i - d*NPIX;
        __half hi, lo; spl(kb[i], hi, lo);
        Khi[p*QTP + d] = hi;
        Klo[p*QTP + d] = lo;
    }
    for (int i = tid; i < VDIM*NPIX; i += 256) {
        int d = i / NPIX, p = i - d*NPIX;
        Vh[d*VHP + p] = __float2half(vb[i]);
    }
    __syncthreads();

    const int w = tid >> 5, lane = tid & 31;
    const int g = lane >> 2, tg = lane & 3;

    for (int tile = w; tile < 25; tile += 8) {
        const int q0 = tile * 16;
        unsigned qh[4], ql[4];
        {
            const int r0 = q0 + g, r1 = q0 + g + 8;
            const int d0 = 2*tg, d1 = 2*tg + 8;
            float q00a = qb[(d0  )*NPIX + r0], q00b = qb[(d0+1)*NPIX + r0];
            float q10a = qb[(d0  )*NPIX + r1], q10b = qb[(d0+1)*NPIX + r1];
            float q01a = qb[(d1  )*NPIX + r0], q01b = qb[(d1+1)*NPIX + r0];
            float q11a = qb[(d1  )*NPIX + r1], q11b = qb[(d1+1)*NPIX + r1];
            __half ha, la, hb2, lb2;
            spl(q00a, ha, la); spl(q00b, hb2, lb2);
            qh[0] = pack2(ha, hb2); ql[0] = pack2(la, lb2);
            spl(q10a, ha, la); spl(q10b, hb2, lb2);
            qh[1] = pack2(ha, hb2); ql[1] = pack2(la, lb2);
            spl(q01a, ha, la); spl(q01b, hb2, lb2);
            qh[2] = pack2(ha, hb2); ql[2] = pack2(la, lb2);
            spl(q11a, ha, la); spl(q11b, hb2, lb2);
            qh[3] = pack2(ha, hb2); ql[3] = pack2(la, lb2);
        }

        float o[8][4];
        #pragma unroll
        for (int dt = 0; dt < 8; dt++)
            #pragma unroll
            for (int i = 0; i < 4; i++) o[dt][i] = 0.f;
        float m_g = -1e30f, m_h = -1e30f, den_g = 0.f, den_h = 0.f;

        const float* bfrag = &g_bias[((((size_t)h*25 + tile)*25)*32 + lane)*8];

        for (int kc = 0; kc < 25; kc++) {
            const int k0 = kc * 16;
            float s0[4] = {0.f,0.f,0.f,0.f};
            float s1[4] = {0.f,0.f,0.f,0.f};
            {
                unsigned b0h = *(const unsigned*)&Khi[(k0+g)*QTP + 2*tg];
                unsigned b1h = *(const unsigned*)&Khi[(k0+g)*QTP + 2*tg + 8];
                unsigned b0l = *(const unsigned*)&Klo[(k0+g)*QTP + 2*tg];
                unsigned b1l = *(const unsigned*)&Klo[(k0+g)*QTP + 2*tg + 8];
                mmah(s0, qh[0], qh[1], qh[2], qh[3], b0h, b1h);
                mmah(s0, qh[0], qh[1], qh[2], qh[3], b0l, b1l);
                mmah(s0, ql[0], ql[1], ql[2], ql[3], b0h, b1h);
                unsigned c0h = *(const unsigned*)&Khi[(k0+8+g)*QTP + 2*tg];
                unsigned c1h = *(const unsigned*)&Khi[(k0+8+g)*QTP + 2*tg + 8];
                unsigned c0l = *(const unsigned*)&Klo[(k0+8+g)*QTP + 2*tg];
                unsigned c1l = *(const unsigned*)&Klo[(k0+8+g)*QTP + 2*tg + 8];
                mmah(s1, qh[0], qh[1], qh[2], qh[3], c0h, c1h);
                mmah(s1, qh[0], qh[1], qh[2], qh[3], c0l, c1l);
                mmah(s1, ql[0], ql[1], ql[2], ql[3], c0h, c1h);
            }
            const float4 bv0 = *(const float4*)(bfrag + (size_t)kc*256);
            const float4 bv1 = *(const float4*)(bfrag + (size_t)kc*256 + 4);
            s0[0] += bv0.x; s0[1] += bv0.y; s0[2] += bv0.z; s0[3] += bv0.w;
            s1[0] += bv1.x; s1[1] += bv1.y; s1[2] += bv1.z; s1[3] += bv1.w;
            float cmg = fmaxf(fmaxf(s0[0], s0[1]), fmaxf(s1[0], s1[1]));
            float cmh = fmaxf(fmaxf(s0[2], s0[3]), fmaxf(s1[2], s1[3]));
            cmg = fmaxf(cmg, __shfl_xor_sync(0xffffffffu, cmg, 1));
            cmg = fmaxf(cmg, __shfl_xor_sync(0xffffffffu, cmg, 2));
            cmh = fmaxf(cmh, __shfl_xor_sync(0xffffffffu, cmh, 1));
            cmh = fmaxf(cmh, __shfl_xor_sync(0xffffffffu, cmh, 2));
            if (__any_sync(0xffffffffu, (cmg > m_g) || (cmh > m_h))) {
                float nm_g = fmaxf(m_g, cmg), nm_h = fmaxf(m_h, cmh);
                float rg = ex2f(m_g - nm_g), rh = ex2f(m_h - nm_h);
                den_g *= rg; den_h *= rh;
                #pragma unroll
                for (int dt = 0; dt < 8; dt++) {
                    o[dt][0] *= rg; o[dt][1] *= rg;
                    o[dt][2] *= rh; o[dt][3] *= rh;
                }
                m_g = nm_g; m_h = nm_h;
            }
            float p00 = ex2f(s0[0] - m_g), p01 = ex2f(s0[1] - m_g);
            float p02 = ex2f(s0[2] - m_h), p03 = ex2f(s0[3] - m_h);
            float p10 = ex2f(s1[0] - m_g), p11 = ex2f(s1[1] - m_g);
            float p12 = ex2f(s1[2] - m_h), p13 = ex2f(s1[3] - m_h);
            den_g += (p00 + p01) + (p10 + p11);
            den_h += (p02 + p03) + (p12 + p13);
            unsigned ph[4], pl[4];
            {
                __half ha, la, hb2, lb2;
                spl(p00, ha, la); spl(p01, hb2, lb2);
                ph[0] = pack2(ha, hb2); pl[0] = pack2(la, lb2);
                spl(p02, ha, la); spl(p03, hb2, lb2);
                ph[1] = pack2(ha, hb2); pl[1] = pack2(la, lb2);
                spl(p10, ha, la); spl(p11, hb2, lb2);
                ph[2] = pack2(ha, hb2); pl[2] = pack2(la, lb2);
                spl(p12, ha, la); spl(p13, hb2, lb2);
                ph[3] = pack2(ha, hb2); pl[3] = pack2(la, lb2);
            }
            #pragma unroll
            for (int dt = 0; dt < 8; dt++) {
                unsigned vb0 = *(const unsigned*)&Vh[(dt*8+g)*VHP + k0 + 2*tg];
                unsigned vb1 = *(const unsigned*)&Vh[(dt*8+g)*VHP + k0 + 2*tg + 8];
                mmah(o[dt], ph[0], ph[1], ph[2], ph[3], vb0, vb1);
                mmah(o[dt], pl[0], pl[1], pl[2], pl[3], vb0, vb1);
            }
        }
        den_g += __shfl_xor_sync(0xffffffffu, den_g, 1);
        den_g += __shfl_xor_sync(0xffffffffu, den_g, 2);
        den_h += __shfl_xor_sync(0xffffffffu, den_h, 1);
        den_h += __shfl_xor_sync(0xffffffffu, den_h, 2);
        const float ig = 1.f / den_g, ih = 1.f / den_h;
        __half* org = &g_oth[((size_t)b*NPIX + q0 + g)*DHD + h*VDIM];
        __half* orh = &g_oth[((size_t)b*NPIX + q0 + g + 8)*DHD + h*VDIM];
        #pragma unroll
        for (int dt = 0; dt < 8; dt++) {
            float v0x = fmaxf(o[dt][0] * ig, 0.f), v0y = fmaxf(o[dt][1] * ig, 0.f);
            float v1x = fmaxf(o[dt][2] * ih, 0.f), v1y = fmaxf(o[dt][3] * ih, 0.f);
            *(__half2*)&org[dt*8 + 2*tg] = __floats2half2_rn(v0x, v0y);
            *(__half2*)&orh[dt*8 + 2*tg] = __floats2half2_rn(v1x, v1y);
        }
    }
}

// ---------------- launch ----------------
extern "C" void kernel_launch(void* const* d_in, const int* in_sizes, int n_in,
                              void* d_out, int out_size) {
    const float* x      = (const float*)d_in[0];
    const float* qkv_w  = (const float*)d_in[1];
    const float* qkv_s  = (const float*)d_in[2];
    const float* qkv_b  = (const float*)d_in[3];
    const float* dw_w   = (const float*)d_in[4];
    const float* dw_s   = (const float*)d_in[5];
    const float* dw_b   = (const float*)d_in[6];
    const float* proj_w = (const float*)d_in[7];
    const float* proj_s = (const float*)d_in[8];
    const float* proj_b = (const float*)d_in[9];
    const float* ab     = (const float*)d_in[10];
    const float* pw1_w  = (const float*)d_in[11];
    const float* pw1_s  = (const float*)d_in[12];
    const float* pw1_b  = (const float*)d_in[13];
    const float* pw2_w  = (const float*)d_in[14];
    const float* pw2_s  = (const float*)d_in[15];
    const float* pw2_b  = (const float*)d_in[16];
    const int*   idxs   = (const int*)d_in[17];

    float *p_qkv, *p_y1;
    __half *p_xh, *p_oth, *p_y1h, *p_hbh, *p_whq, *p_whp, *p_wh1, *p_wh2;
    cudaGetSymbolAddress((void**)&p_qkv, g_qkv);
    cudaGetSymbolAddress((void**)&p_y1,  g_y1);
    cudaGetSymbolAddress((void**)&p_xh,  g_xh);
    cudaGetSymbolAddress((void**)&p_oth, g_oth);
    cudaGetSymbolAddress((void**)&p_y1h, g_y1h);
    cudaGetSymbolAddress((void**)&p_hbh, g_hbh);
    cudaGetSymbolAddress((void**)&p_whq, g_whq);
    cudaGetSymbolAddress((void**)&p_whp, g_whp);
    cudaGetSymbolAddress((void**)&p_wh1, g_wh1);
    cudaGetSymbolAddress((void**)&p_wh2, g_wh2);

    // side stream + events, created once (thread-safe static init; identical
    // captured work every call)
    static cudaStream_t s2 = [](){
        cudaStream_t s; cudaStreamCreateWithFlags(&s, cudaStreamNonBlocking); return s;
    }();
    static cudaEvent_t eF = [](){
        cudaEvent_t e; cudaEventCreateWithFlags(&e, cudaEventDisableTiming); return e;
    }();
    static cudaEvent_t eJ = [](){
        cudaEvent_t e; cudaEventCreateWithFlags(&e, cudaEventDisableTiming); return e;
    }();

    // ---- fork side stream off the capture origin (stream 0) ----
    cudaEventRecord(eF, 0);
    cudaStreamWaitEvent(s2, eF, 0);

    // ---- side stream: bias pipeline + late-weight converts (indep of main) ----
    k_mtaps<<<1, 512, 0, s2>>>();
    k_bias1<<<(NHEAD*NPIX*SPIX + 255)/256, 256, 0, s2>>>(ab, idxs);
    k_bias2<<<(NHEAD*25*25*32*8 + 255)/256, 256, 0, s2>>>();
    k_cvtw<<<(EDIM*DHD/4 + 255)/256, 256, 0, s2>>>(proj_w, p_whp, EDIM*DHD/4);
    k_cvtw<<<(DHD*EDIM/4 + 255)/256, 256, 0, s2>>>(pw1_w,  p_wh1, DHD*EDIM/4);
    k_cvtw<<<(EDIM*DHD/4 + 255)/256, 256, 0, s2>>>(pw2_w,  p_wh2, EDIM*DHD/4);
    cudaEventRecord(eJ, s2);

    // ---- main stream (0): critical path ----
    k_cvtx<<<(NB*EDIM*NPIX + 255)/256, 256>>>(x);
    k_cvtw<<<(HQ*EDIM/4 + 255)/256, 256>>>(qkv_w, p_whq, HQ*EDIM/4);
    k_gemm_f<<<dim3(7, HQ/128, NB), 256>>>(p_xh, p_whq, qkv_s, qkv_b,
                                           nullptr, p_qkv, nullptr, HQ, EDIM, 0);
    k_dwconv<<<(NB*128*NPIX + 255)/256, 256>>>(dw_w, dw_s, dw_b);

    // ---- join: attention needs g_bias; proj/pw1/pw2 need whp/wh1/wh2 ----
    cudaStreamWaitEvent(0, eJ, 0);

    const int smem = (9600 + 9600 + VDIM*VHP) * 2;  // 90624 B
    cudaFuncSetAttribute(k_attn6, cudaFuncAttributeMaxDynamicSharedMemorySize, smem);
    k_attn6<<<NB*NHEAD, 256, smem>>>();

    k_gemm_f<<<dim3(7, EDIM/128, NB), 256>>>(p_oth, p_whp, proj_s, proj_b,
                                             x, p_y1, p_y1h, EDIM, DHD, 0);
    k_gemm_f<<<dim3(7, DHD/128, NB), 256>>>(p_y1h, p_wh1, pw1_s, pw1_b,
                                            nullptr, nullptr, p_hbh, DHD, EDIM, 1);
    k_gemm_f<<<dim3(7, EDIM/128, NB), 256>>>(p_hbh, p_wh2, pw2_s, pw2_b,
                                             p_y1, (float*)d_out, nullptr, EDIM, DHD, 0);
}

// round 16
// speedup vs baseline: 1.4588x; 1.0597x over previous
#include <cuda_runtime.h>
#include <cuda_fp16.h>
#include <math.h>

#define NB    32
#define EDIM  256
#define NHEAD 8
#define KDIM  16
#define VDIM  64
#define DHD   512
#define HQ    768
#define NPIX  400
#define SPIX  196
#define TSP   40    // GEMM smem tile row stride (halves)
#define QTP   24    // Khi/Klo row stride (halves)
#define VHP   408   // Vh row stride (halves)
#define QSC   0.3606737602222409f   // 0.25 * log2(e)
#define L2E   1.4426950408889634f

typedef unsigned long long ull;

__device__ __forceinline__ float ex2f(float x) {
    float y; asm("ex2.approx.ftz.f32 %0, %1;" : "=f"(y) : "f"(x)); return y;
}
__device__ __forceinline__ void mmah(float* c, unsigned a0, unsigned a1, unsigned a2, unsigned a3,
                                     unsigned b0, unsigned b1) {
    asm volatile("mma.sync.aligned.m16n8k16.row.col.f32.f16.f16.f32 "
        "{%0,%1,%2,%3}, {%4,%5,%6,%7}, {%8,%9}, {%0,%1,%2,%3};"
        : "+f"(c[0]), "+f"(c[1]), "+f"(c[2]), "+f"(c[3])
        : "r"(a0), "r"(a1), "r"(a2), "r"(a3), "r"(b0), "r"(b1));
}
__device__ __forceinline__ void ldsm4(unsigned& r0, unsigned& r1, unsigned& r2, unsigned& r3,
                                      unsigned addr) {
    asm volatile("ldmatrix.sync.aligned.m8n8.x4.shared.b16 {%0,%1,%2,%3}, [%4];"
        : "=r"(r0), "=r"(r1), "=r"(r2), "=r"(r3) : "r"(addr));
}
// pack {lo, hi} floats into f16x2 (cvt packs FIRST source into the upper half)
__device__ __forceinline__ unsigned packh2(float lo, float hi) {
    unsigned d; asm("cvt.rn.f16x2.f32 %0, %1, %2;" : "=r"(d) : "f"(hi), "f"(lo)); return d;
}
__device__ __forceinline__ void spl(float x, __half& hi, __half& lo) {
    hi = __float2half(x);
    lo = __float2half(x - __half2float(hi));
}
__device__ __forceinline__ unsigned pack2(__half a, __half b) {
    return (unsigned)__half_as_ushort(a) | ((unsigned)__half_as_ushort(b) << 16);
}
__device__ __forceinline__ unsigned saddr(const void* p) {
    return (unsigned)__cvta_generic_to_shared(p);
}
__device__ __forceinline__ void cpa16(unsigned dst, const void* src, int src_bytes) {
    asm volatile("cp.async.ca.shared.global [%0], [%1], 16, %2;"
        :: "r"(dst), "l"(src), "r"(src_bytes));
}
__device__ __forceinline__ void cpa_commit() { asm volatile("cp.async.commit_group;"); }
template<int N> __device__ __forceinline__ void cpa_wait() {
    asm volatile("cp.async.wait_group %0;" :: "n"(N));
}

// ---------------- device scratch ----------------
__device__ __align__(16) float  g_qkv [NB*HQ*NPIX];
__device__ __align__(16) float  g_qdw [NB*128*NPIX];     // pre-scaled by QSC
__device__ __align__(16) float  g_tmpb[NHEAD*NPIX*SPIX];
__device__ __align__(16) float  g_bias[NHEAD*NPIX*NPIX]; // fragment layout, *L2E
__device__ __align__(16) float  g_y1  [NB*EDIM*NPIX];    // f32 proj residual output
__device__ __align__(16) __half g_xh  [NB*NPIX*EDIM];    // x transposed f16 [b][p][ci]
__device__ __align__(16) __half g_oth [NB*NPIX*DHD];     // relu(attention out) f16 [b][p][hd]
__device__ __align__(16) __half g_y1h [NB*NPIX*EDIM];    // y1 f16 [b][p][o]
__device__ __align__(16) __half g_hbh [NB*NPIX*DHD];     // relu(pw1) f16 [b][p][o]
__device__ __align__(16) __half g_whq [HQ*EDIM];
__device__ __align__(16) __half g_whp [EDIM*DHD];
__device__ __align__(16) __half g_wh1 [DHD*EDIM];
__device__ __align__(16) __half g_wh2 [EDIM*DHD];
__device__ int   g_midx[NPIX*4];
__device__ float g_mw  [NPIX*4];

// ---------------- setup converts ----------------
__global__ void k_cvtw(const float* __restrict__ src, __half* __restrict__ dst, int n4) {
    int i = blockIdx.x*blockDim.x + threadIdx.x;
    if (i >= n4) return;
    float4 v = *(const float4*)&src[i*4];
    __half h[4] = {__float2half(v.x), __float2half(v.y), __float2half(v.z), __float2half(v.w)};
    *(ull*)&dst[i*4] = *(ull*)h;
}
// xh[b][p][ci] = f16(x[b][ci][p])
__global__ void k_cvtx(const float* __restrict__ x) {
    int i = blockIdx.x*blockDim.x + threadIdx.x;
    if (i >= NB*EDIM*NPIX) return;
    int p  = i % NPIX;
    int ci = (i / NPIX) % EDIM;
    int b  = i / (EDIM*NPIX);
    g_xh[((size_t)b*NPIX + p)*EDIM + ci] = __float2half(x[i]);
}

// ---------------- bicubic taps ----------------
__global__ void k_mtaps() {
    int i = blockIdx.x*blockDim.x + threadIdx.x;
    if (i >= NPIX) return;
    double scale = (double)SPIX / (double)NPIX;
    double src = (i + 0.5)*scale - 0.5;
    double f = floor(src);
    double t = src - f;
    const double a = -0.75;
    for (int j = -1; j <= 2; j++) {
        double xx = fabs((double)j - t);
        double w;
        if (xx <= 1.0)      w = (a+2.0)*xx*xx*xx - (a+3.0)*xx*xx + 1.0;
        else if (xx < 2.0)  w = a*xx*xx*xx - 5.0*a*xx*xx + 8.0*a*xx - 4.0*a;
        else                w = 0.0;
        int idx = (int)f + j;
        idx = min(max(idx, 0), SPIX-1);
        g_midx[i*4 + (j+1)] = idx;
        g_mw  [i*4 + (j+1)] = (float)w;
    }
}

__global__ void k_bias1(const float* __restrict__ ab, const int* __restrict__ idxs) {
    int i = blockIdx.x*blockDim.x + threadIdx.x;
    if (i >= NHEAD*NPIX*SPIX) return;
    int t = i % SPIX;
    int n = (i / SPIX) % NPIX;
    int h = i / (SPIX*NPIX);
    float acc = 0.f;
    #pragma unroll
    for (int k = 0; k < 4; k++) {
        int s = g_midx[n*4+k];
        acc += g_mw[n*4+k] * ab[h*SPIX + idxs[s*SPIX + t]];
    }
    g_tmpb[i] = acc;
}

// bias in m16n8k16 C-fragment order: out[h][qt][kc][lane][j] = L2E * bias(h,q,k)
__global__ void k_bias2() {
    int i = blockIdx.x*blockDim.x + threadIdx.x;
    if (i >= NHEAD*25*25*32*8) return;
    int j    = i & 7;
    int lane = (i >> 3) & 31;
    int kc   = (i >> 8) % 25;
    int qt   = ((i >> 8) / 25) % 25;
    int h    = (i >> 8) / 625;
    int g = lane >> 2, tg = lane & 3;
    int dr = ((j >> 1) & 1) * 8;
    int dc = 2*tg + (j & 1) + ((j >= 4) ? 8 : 0);
    int q = qt*16 + g + dr;
    int k = kc*16 + dc;
    const float* trow = g_tmpb + ((size_t)h*NPIX + q)*SPIX;
    float acc = 0.f;
    #pragma unroll
    for (int kk = 0; kk < 4; kk++)
        acc += g_mw[k*4+kk] * trow[g_midx[k*4+kk]];
    g_bias[i] = acc * L2E;
}

// ---------------- depthwise 3x3 (output pre-scaled by QSC) ----------------
__global__ void k_dwconv(const float* __restrict__ w, const float* __restrict__ s,
                         const float* __restrict__ bia) {
    int i = blockIdx.x*blockDim.x + threadIdx.x;
    if (i >= NB*128*NPIX) return;
    int p = i % NPIX;
    int c = (i / NPIX) % 128;
    int b = i / (128*NPIX);
    int y = p / 20, x = p % 20;
    const float* src = g_qkv + ((size_t)b*HQ + c)*NPIX;
    float acc = 0.f;
    #pragma unroll
    for (int dy = -1; dy <= 1; dy++) {
        int yy = y + dy;
        if (yy < 0 || yy >= 20) continue;
        #pragma unroll
        for (int dx = -1; dx <= 1; dx++) {
            int xx = x + dx;
            if (xx < 0 || xx >= 20) continue;
            acc += w[c*9 + (dy+1)*3 + (dx+1)] * src[yy*20 + xx];
        }
    }
    g_qdw[i] = (acc * s[c] + bia[c]) * QSC;
}

// ---------------- all-f16 GEMM: 3-stage cp.async + ldmatrix ----------------
// One __syncthreads per chunk; prefetch distance 2 hides the LDG latency.
__global__ void __launch_bounds__(256, 3) k_gemm_f(
    const __half* __restrict__ X, const __half* __restrict__ W,
    const float* __restrict__ sc, const float* __restrict__ bi,
    const float* __restrict__ R, float* __restrict__ Yf, __half* __restrict__ Yh,
    int O, int Cin, int relu)
{
    __shared__ __align__(16) __half Ws[3][128*TSP];
    __shared__ __align__(16) __half Xs[3][64*TSP];
    const int b  = blockIdx.z;
    const int oT = blockIdx.y * 128;
    const int pT = blockIdx.x * 64;
    const int t  = threadIdx.x;
    const int wid = t >> 5, lane = t & 31;
    const int g = lane >> 2, tg = lane & 3;
    const int warpM = wid & 3, warpN = wid >> 2;

    float acc[2][4][4];
    #pragma unroll
    for (int mt = 0; mt < 2; mt++)
        #pragma unroll
        for (int nt = 0; nt < 4; nt++)
            #pragma unroll
            for (int i = 0; i < 4; i++) acc[mt][nt][i] = 0.f;

    const int nchunk = Cin >> 5;

    const int wRow0 = t >> 2, wSeg0 = (t & 3) * 8;
    const int wRow1 = wRow0 + 64;
    const int xRow  = t >> 2, xSeg = (t & 3) * 8;
    const int xP    = pT + xRow;
    const __half* Wb0 = &W[(size_t)(oT + wRow0)*Cin + wSeg0];
    const __half* Wb1 = &W[(size_t)(oT + wRow1)*Cin + wSeg0];
    const __half* Xb  = &X[((size_t)b*NPIX + xP)*Cin + xSeg];
    const int xBytes = (xP < NPIX) ? 16 : 0;

    #define COPY_CHUNK(k0, buf)                                          \
    {                                                                    \
        cpa16(saddr(&Ws[buf][wRow0*TSP + wSeg0]), Wb0 + (k0), 16);       \
        cpa16(saddr(&Ws[buf][wRow1*TSP + wSeg0]), Wb1 + (k0), 16);       \
        cpa16(saddr(&Xs[buf][xRow*TSP + xSeg]),  Xb  + (k0), xBytes);    \
        cpa_commit();                                                    \
    }

    COPY_CHUNK(0, 0);
    COPY_CHUNK(32, 1);

    const int rA = (lane & 7) + ((lane >> 3) & 1) * 8;
    const int cA = ((lane >> 4) & 1) * 8;
    const int rB = (lane & 7) + ((lane >> 4) & 1) * 8;
    const int cB = ((lane >> 3) & 1) * 8;

    int bufC = 0, bufL = 2;
    for (int c = 0; c < nchunk; c++) {
        // chunk c complete when <=1 groups pending (c+1 may still be in flight)
        if (c + 1 < nchunk) cpa_wait<1>(); else cpa_wait<0>();
        __syncthreads();   // also orders compute c-1 before overwriting its buffer
        if (c + 2 < nchunk) {
            COPY_CHUNK((c+2)*32, bufL);
            bufL = (bufL == 2) ? 0 : bufL + 1;
        }

        #pragma unroll
        for (int ks = 0; ks < 2; ks++) {
            const int kk = ks * 16;
            unsigned a[2][4], bm[2][4];
            #pragma unroll
            for (int mt = 0; mt < 2; mt++)
                ldsm4(a[mt][0], a[mt][1], a[mt][2], a[mt][3],
                      saddr(&Ws[bufC][(warpM*32 + mt*16 + rA)*TSP + kk + cA]));
            #pragma unroll
            for (int ntp = 0; ntp < 2; ntp++)
                ldsm4(bm[ntp][0], bm[ntp][1], bm[ntp][2], bm[ntp][3],
                      saddr(&Xs[bufC][(warpN*32 + ntp*16 + rB)*TSP + kk + cB]));
            #pragma unroll
            for (int mt = 0; mt < 2; mt++)
                #pragma unroll
                for (int ntp = 0; ntp < 2; ntp++) {
                    mmah(acc[mt][2*ntp],   a[mt][0], a[mt][1], a[mt][2], a[mt][3],
                         bm[ntp][0], bm[ntp][1]);
                    mmah(acc[mt][2*ntp+1], a[mt][0], a[mt][1], a[mt][2], a[mt][3],
                         bm[ntp][2], bm[ntp][3]);
                }
        }
        bufC = (bufC == 2) ? 0 : bufC + 1;
    }
    #undef COPY_CHUNK

    #pragma unroll
    for (int mt = 0; mt < 2; mt++) {
        const int o0 = oT + warpM*32 + mt*16 + g;
        const int o1 = o0 + 8;
        const float s0 = sc[o0], bb0 = bi[o0];
        const float s1 = sc[o1], bb1 = bi[o1];
        #pragma unroll
        for (int nt = 0; nt < 4; nt++) {
            const int p = pT + warpN*32 + nt*8 + 2*tg;
            if (p < NPIX) {
                float2 v0, v1;
                v0.x = acc[mt][nt][0]*s0 + bb0;
                v0.y = acc[mt][nt][1]*s0 + bb0;
                v1.x = acc[mt][nt][2]*s1 + bb1;
                v1.y = acc[mt][nt][3]*s1 + bb1;
                const size_t off0 = ((size_t)b*O + o0)*NPIX + p;
                const size_t off1 = ((size_t)b*O + o1)*NPIX + p;
                if (R) {
                    float2 r0 = *(const float2*)&R[off0];
                    float2 r1 = *(const float2*)&R[off1];
                    v0.x += r0.x; v0.y += r0.y;
                    v1.x += r1.x; v1.y += r1.y;
                }
                if (relu) {
                    v0.x = fmaxf(v0.x,0.f); v0.y = fmaxf(v0.y,0.f);
                    v1.x = fmaxf(v1.x,0.f); v1.y = fmaxf(v1.y,0.f);
                }
                if (Yf) {
                    *(float2*)&Yf[off0] = v0;
                    *(float2*)&Yf[off1] = v1;
                }
                if (Yh) {
                    __half* yr0 = &Yh[((size_t)b*NPIX + p)*O];
                    __half* yr1 = yr0 + O;
                    yr0[o0] = __float2half(v0.x);
                    yr1[o0] = __float2half(v0.y);
                    yr0[o1] = __float2half(v1.x);
                    yr1[o1] = __float2half(v1.y);
                }
            }
        }
    }
}

// ---------------- tensor-core flash attention ----------------
// QK: 3-term split-f16 (score error ~2^-21). P: single f16 (adds ~3e-4).
// PV: 8 mmas per chunk. Output: g_oth f16, relu fused.
__global__ void __launch_bounds__(256, 2) k_attn6() {
    extern __shared__ __half smh[];
    __half* Khi = smh;              // [400][QTP]
    __half* Klo = smh + 9600;       // [400][QTP]
    __half* Vh  = smh + 19200;      // [64][VHP]
    const int bh = blockIdx.x;
    const int b = bh >> 3, h = bh & 7;
    const int tid = threadIdx.x;

    const float* qb = g_qdw + ((size_t)b*128 + h*KDIM)*NPIX;
    const float* kb = g_qkv + ((size_t)b*HQ + 128 + h*KDIM)*NPIX;
    const float* vb = g_qkv + ((size_t)b*HQ + 256 + h*VDIM)*NPIX;

    for (int i = tid; i < KDIM*NPIX; i += 256) {
        int d = i / NPIX, p = i - d*NPIX;
        __half hi, lo; spl(kb[i], hi, lo);
        Khi[p*QTP + d] = hi;
        Klo[p*QTP + d] = lo;
    }
    for (int i = tid; i < VDIM*NPIX; i += 256) {
        int d = i / NPIX, p = i - d*NPIX;
        Vh[d*VHP + p] = __float2half(vb[i]);
    }
    __syncthreads();

    const int w = tid >> 5, lane = tid & 31;
    const int g = lane >> 2, tg = lane & 3;

    for (int tile = w; tile < 25; tile += 8) {
        const int q0 = tile * 16;
        unsigned qh[4], ql[4];
        {
            const int r0 = q0 + g, r1 = q0 + g + 8;
            const int d0 = 2*tg, d1 = 2*tg + 8;
            float q00a = qb[(d0  )*NPIX + r0], q00b = qb[(d0+1)*NPIX + r0];
            float q10a = qb[(d0  )*NPIX + r1], q10b = qb[(d0+1)*NPIX + r1];
            float q01a = qb[(d1  )*NPIX + r0], q01b = qb[(d1+1)*NPIX + r0];
            float q11a = qb[(d1  )*NPIX + r1], q11b = qb[(d1+1)*NPIX + r1];
            __half ha, la, hb2, lb2;
            spl(q00a, ha, la); spl(q00b, hb2, lb2);
            qh[0] = pack2(ha, hb2); ql[0] = pack2(la, lb2);
            spl(q10a, ha, la); spl(q10b, hb2, lb2);
            qh[1] = pack2(ha, hb2); ql[1] = pack2(la, lb2);
            spl(q01a, ha, la); spl(q01b, hb2, lb2);
            qh[2] = pack2(ha, hb2); ql[2] = pack2(la, lb2);
            spl(q11a, ha, la); spl(q11b, hb2, lb2);
            qh[3] = pack2(ha, hb2); ql[3] = pack2(la, lb2);
        }

        float o[8][4];
        #pragma unroll
        for (int dt = 0; dt < 8; dt++)
            #pragma unroll
            for (int i = 0; i < 4; i++) o[dt][i] = 0.f;
        float m_g = -1e30f, m_h = -1e30f, den_g = 0.f, den_h = 0.f;

        const float* bfrag = &g_bias[((((size_t)h*25 + tile)*25)*32 + lane)*8];

        for (int kc = 0; kc < 25; kc++) {
            const int k0 = kc * 16;
            float s0[4] = {0.f,0.f,0.f,0.f};
            float s1[4] = {0.f,0.f,0.f,0.f};
            {
                unsigned b0h = *(const unsigned*)&Khi[(k0+g)*QTP + 2*tg];
                unsigned b1h = *(const unsigned*)&Khi[(k0+g)*QTP + 2*tg + 8];
                unsigned b0l = *(const unsigned*)&Klo[(k0+g)*QTP + 2*tg];
                unsigned b1l = *(const unsigned*)&Klo[(k0+g)*QTP + 2*tg + 8];
                mmah(s0, qh[0], qh[1], qh[2], qh[3], b0h, b1h);
                mmah(s0, qh[0], qh[1], qh[2], qh[3], b0l, b1l);
                mmah(s0, ql[0], ql[1], ql[2], ql[3], b0h, b1h);
                unsigned c0h = *(const unsigned*)&Khi[(k0+8+g)*QTP + 2*tg];
                unsigned c1h = *(const unsigned*)&Khi[(k0+8+g)*QTP + 2*tg + 8];
                unsigned c0l = *(const unsigned*)&Klo[(k0+8+g)*QTP + 2*tg];
                unsigned c1l = *(const unsigned*)&Klo[(k0+8+g)*QTP + 2*tg + 8];
                mmah(s1, qh[0], qh[1], qh[2], qh[3], c0h, c1h);
                mmah(s1, qh[0], qh[1], qh[2], qh[3], c0l, c1l);
                mmah(s1, ql[0], ql[1], ql[2], ql[3], c0h, c1h);
            }
            const float4 bv0 = *(const float4*)(bfrag + (size_t)kc*256);
            const float4 bv1 = *(const float4*)(bfrag + (size_t)kc*256 + 4);
            s0[0] += bv0.x; s0[1] += bv0.y; s0[2] += bv0.z; s0[3] += bv0.w;
            s1[0] += bv1.x; s1[1] += bv1.y; s1[2] += bv1.z; s1[3] += bv1.w;
            float cmg = fmaxf(fmaxf(s0[0], s0[1]), fmaxf(s1[0], s1[1]));
            float cmh = fmaxf(fmaxf(s0[2], s0[3]), fmaxf(s1[2], s1[3]));
            cmg = fmaxf(cmg, __shfl_xor_sync(0xffffffffu, cmg, 1));
            cmg = fmaxf(cmg, __shfl_xor_sync(0xffffffffu, cmg, 2));
            cmh = fmaxf(cmh, __shfl_xor_sync(0xffffffffu, cmh, 1));
            cmh = fmaxf(cmh, __shfl_xor_sync(0xffffffffu, cmh, 2));
            if (__any_sync(0xffffffffu, (cmg > m_g) || (cmh > m_h))) {
                float nm_g = fmaxf(m_g, cmg), nm_h = fmaxf(m_h, cmh);
                float rg = ex2f(m_g - nm_g), rh = ex2f(m_h - nm_h);
                den_g *= rg; den_h *= rh;
                #pragma unroll
                for (int dt = 0; dt < 8; dt++) {
                    o[dt][0] *= rg; o[dt][1] *= rg;
                    o[dt][2] *= rh; o[dt][3] *= rh;
                }
                m_g = nm_g; m_h = nm_h;
            }
            float p00 = ex2f(s0[0] - m_g), p01 = ex2f(s0[1] - m_g);
            float p02 = ex2f(s0[2] - m_h), p03 = ex2f(s0[3] - m_h);
            float p10 = ex2f(s1[0] - m_g), p11 = ex2f(s1[1] - m_g);
            float p12 = ex2f(s1[2] - m_h), p13 = ex2f(s1[3] - m_h);
            den_g += (p00 + p01) + (p10 + p11);
            den_h += (p02 + p03) + (p12 + p13);
            // single-f16 P fragments (adds ~3e-4; within budget)
            unsigned ph0 = packh2(p00, p01);
            unsigned ph1 = packh2(p02, p03);
            unsigned ph2 = packh2(p10, p11);
            unsigned ph3 = packh2(p12, p13);
            #pragma unroll
            for (int dt = 0; dt < 8; dt++) {
                unsigned vb0 = *(const unsigned*)&Vh[(dt*8+g)*VHP + k0 + 2*tg];
                unsigned vb1 = *(const unsigned*)&Vh[(dt*8+g)*VHP + k0 + 2*tg + 8];
                mmah(o[dt], ph0, ph1, ph2, ph3, vb0, vb1);
            }
        }
        den_g += __shfl_xor_sync(0xffffffffu, den_g, 1);
        den_g += __shfl_xor_sync(0xffffffffu, den_g, 2);
        den_h += __shfl_xor_sync(0xffffffffu, den_h, 1);
        den_h += __shfl_xor_sync(0xffffffffu, den_h, 2);
        const float ig = 1.f / den_g, ih = 1.f / den_h;
        __half* org = &g_oth[((size_t)b*NPIX + q0 + g)*DHD + h*VDIM];
        __half* orh = &g_oth[((size_t)b*NPIX + q0 + g + 8)*DHD + h*VDIM];
        #pragma unroll
        for (int dt = 0; dt < 8; dt++) {
            float v0x = fmaxf(o[dt][0] * ig, 0.f), v0y = fmaxf(o[dt][1] * ig, 0.f);
            float v1x = fmaxf(o[dt][2] * ih, 0.f), v1y = fmaxf(o[dt][3] * ih, 0.f);
            *(__half2*)&org[dt*8 + 2*tg] = __floats2half2_rn(v0x, v0y);
            *(__half2*)&orh[dt*8 + 2*tg] = __floats2half2_rn(v1x, v1y);
        }
    }
}

// ---------------- launch ----------------
extern "C" void kernel_launch(void* const* d_in, const int* in_sizes, int n_in,
                              void* d_out, int out_size) {
    const float* x      = (const float*)d_in[0];
    const float* qkv_w  = (const float*)d_in[1];
    const float* qkv_s  = (const float*)d_in[2];
    const float* qkv_b  = (const float*)d_in[3];
    const float* dw_w   = (const float*)d_in[4];
    const float* dw_s   = (const float*)d_in[5];
    const float* dw_b   = (const float*)d_in[6];
    const float* proj_w = (const float*)d_in[7];
    const float* proj_s = (const float*)d_in[8];
    const float* proj_b = (const float*)d_in[9];
    const float* ab     = (const float*)d_in[10];
    const float* pw1_w  = (const float*)d_in[11];
    const float* pw1_s  = (const float*)d_in[12];
    const float* pw1_b  = (const float*)d_in[13];
    const float* pw2_w  = (const float*)d_in[14];
    const float* pw2_s  = (const float*)d_in[15];
    const float* pw2_b  = (const float*)d_in[16];
    const int*   idxs   = (const int*)d_in[17];

    float *p_qkv, *p_y1;
    __half *p_xh, *p_oth, *p_y1h, *p_hbh, *p_whq, *p_whp, *p_wh1, *p_wh2;
    cudaGetSymbolAddress((void**)&p_qkv, g_qkv);
    cudaGetSymbolAddress((void**)&p_y1,  g_y1);
    cudaGetSymbolAddress((void**)&p_xh,  g_xh);
    cudaGetSymbolAddress((void**)&p_oth, g_oth);
    cudaGetSymbolAddress((void**)&p_y1h, g_y1h);
    cudaGetSymbolAddress((void**)&p_hbh, g_hbh);
    cudaGetSymbolAddress((void**)&p_whq, g_whq);
    cudaGetSymbolAddress((void**)&p_whp, g_whp);
    cudaGetSymbolAddress((void**)&p_wh1, g_wh1);
    cudaGetSymbolAddress((void**)&p_wh2, g_wh2);

    static cudaStream_t s2 = [](){
        cudaStream_t s; cudaStreamCreateWithFlags(&s, cudaStreamNonBlocking); return s;
    }();
    static cudaEvent_t eF = [](){
        cudaEvent_t e; cudaEventCreateWithFlags(&e, cudaEventDisableTiming); return e;
    }();
    static cudaEvent_t eJ = [](){
        cudaEvent_t e; cudaEventCreateWithFlags(&e, cudaEventDisableTiming); return e;
    }();

    // ---- fork side stream off the capture origin ----
    cudaEventRecord(eF, 0);
    cudaStreamWaitEvent(s2, eF, 0);

    // ---- side stream: bias pipeline + late-weight converts ----
    k_mtaps<<<1, 512, 0, s2>>>();
    k_bias1<<<(NHEAD*NPIX*SPIX + 255)/256, 256, 0, s2>>>(ab, idxs);
    k_bias2<<<(NHEAD*25*25*32*8 + 255)/256, 256, 0, s2>>>();
    k_cvtw<<<(EDIM*DHD/4 + 255)/256, 256, 0, s2>>>(proj_w, p_whp, EDIM*DHD/4);
    k_cvtw<<<(DHD*EDIM/4 + 255)/256, 256, 0, s2>>>(pw1_w,  p_wh1, DHD*EDIM/4);
    k_cvtw<<<(EDIM*DHD/4 + 255)/256, 256, 0, s2>>>(pw2_w,  p_wh2, EDIM*DHD/4);
    cudaEventRecord(eJ, s2);

    // ---- main stream: critical path ----
    k_cvtx<<<(NB*EDIM*NPIX + 255)/256, 256>>>(x);
    k_cvtw<<<(HQ*EDIM/4 + 255)/256, 256>>>(qkv_w, p_whq, HQ*EDIM/4);
    k_gemm_f<<<dim3(7, HQ/128, NB), 256>>>(p_xh, p_whq, qkv_s, qkv_b,
                                           nullptr, p_qkv, nullptr, HQ, EDIM, 0);
    k_dwconv<<<(NB*128*NPIX + 255)/256, 256>>>(dw_w, dw_s, dw_b);

    // ---- join ----
    cudaStreamWaitEvent(0, eJ, 0);

    const int smem = (9600 + 9600 + VDIM*VHP) * 2;  // 90624 B
    cudaFuncSetAttribute(k_attn6, cudaFuncAttributeMaxDynamicSharedMemorySize, smem);
    k_attn6<<<NB*NHEAD, 256, smem>>>();

    k_gemm_f<<<dim3(7, EDIM/128, NB), 256>>>(p_oth, p_whp, proj_s, proj_b,
                                             x, p_y1, p_y1h, EDIM, DHD, 0);
    k_gemm_f<<<dim3(7, DHD/128, NB), 256>>>(p_y1h, p_wh1, pw1_s, pw1_b,
                                            nullptr, nullptr, p_hbh, DHD, EDIM, 1);
    k_gemm_f<<<dim3(7, EDIM/128, NB), 256>>>(p_hbh, p_wh2, pw2_s, pw2_b,
                                             p_y1, (float*)d_out, nullptr, EDIM, DHD, 0);
}